// round 1
// baseline (speedup 1.0000x reference)
#include <cuda_runtime.h>
#include <math.h>

#define NMAX 50000
#define EMAX 800000
#define ETMAX (EMAX + NMAX)

// ---------------- scratch (device globals; no allocation allowed) ------------
__device__ float g_h1[NMAX * 256];      // GAT1 transformed features
__device__ float g_asrc1[NMAX * 8];
__device__ float g_adst1[NMAX * 8];
__device__ float g_den1[NMAX * 8];
__device__ float g_out1[NMAX * 256];    // GAT1 output -> ELU in place -> x2
__device__ float g_h2[NMAX * 16];
__device__ float g_asrc2[NMAX];
__device__ float g_adst2[NMAX];
__device__ float g_den2[NMAX];
__device__ float g_out2[NMAX * 16];     // GAT2 output -> ELU in place -> x3
__device__ float g_deg[NMAX];
__device__ float g_dinv[NMAX];
__device__ float g_g[NMAX * 16];        // (x3@W3) * dinv[src]

__device__ __forceinline__ float lrelu(float x) { return x > 0.f ? x : 0.2f * x; }

__device__ __forceinline__ void red_add_v4(float* p, float a, float b, float c, float d) {
    asm volatile("red.global.add.v4.f32 [%0], {%1,%2,%3,%4};"
                 :: "l"(p), "f"(a), "f"(b), "f"(c), "f"(d) : "memory");
}

// ---------------- GEMM1: h1 = x[ N,128 ] @ W1[128,256] ----------------------
__global__ void k_gemm1(const float* __restrict__ x, const float* __restrict__ W1,
                        float* __restrict__ h1, int N) {
    __shared__ float xsT[128][68];           // transposed tile, padded
    const int t = threadIdx.x;               // 256 threads
    const int r0 = blockIdx.x * 64;
#pragma unroll
    for (int i = 0; i < 32; i++) {
        int lin = i * 256 + t;
        int r = lin >> 7, k = lin & 127;
        float v = (r0 + r < N) ? x[(size_t)(r0 + r) * 128 + k] : 0.f;
        xsT[k][r] = v;
    }
    __syncthreads();
    float acc[64];
#pragma unroll
    for (int i = 0; i < 64; i++) acc[i] = 0.f;
    const int col = t;
    for (int k = 0; k < 128; k++) {
        float w = W1[k * 256 + col];
        const float4* xr = reinterpret_cast<const float4*>(xsT[k]);
#pragma unroll
        for (int r4 = 0; r4 < 16; r4++) {
            float4 xv = xr[r4];
            acc[4 * r4 + 0] += xv.x * w;
            acc[4 * r4 + 1] += xv.y * w;
            acc[4 * r4 + 2] += xv.z * w;
            acc[4 * r4 + 3] += xv.w * w;
        }
    }
    for (int r = 0; r < 64; r++) {
        if (r0 + r < N) h1[(size_t)(r0 + r) * 256 + col] = acc[r];
    }
}

// ----- alpha projections for GAT1: asrc1[n,h] = <h1[n,h,:], a_src1[h,:]> -----
__global__ void k_alpha1(const float* __restrict__ h1, const float* __restrict__ a_src,
                         const float* __restrict__ a_dst, float* __restrict__ asrcn,
                         float* __restrict__ adstn, int N) {
    int i = blockIdx.x * blockDim.x + threadIdx.x;  // over N*8
    if (i >= N * 8) return;
    int h = i & 7;
    const float4* hp = reinterpret_cast<const float4*>(h1 + (size_t)i * 32);
    const float4* as = reinterpret_cast<const float4*>(a_src + h * 32);
    const float4* ad = reinterpret_cast<const float4*>(a_dst + h * 32);
    float s = 0.f, d = 0.f;
#pragma unroll
    for (int j = 0; j < 8; j++) {
        float4 hv = hp[j], av = as[j], dv = ad[j];
        s += hv.x * av.x + hv.y * av.y + hv.z * av.z + hv.w * av.w;
        d += hv.x * dv.x + hv.y * dv.y + hv.z * dv.z + hv.w * dv.w;
    }
    asrcn[i] = s;
    adstn[i] = d;
}

// ----- GAT1 softmax denominator + GCN in-degree (fused) ---------------------
__global__ void k_den1(const int* __restrict__ ei, int E, int N,
                       const float* __restrict__ asrcn, const float* __restrict__ adstn,
                       float* __restrict__ den1, float* __restrict__ deg) {
    int e = blockIdx.x * blockDim.x + threadIdx.x;
    int ET = E + N;
    if (e >= ET) return;
    int s, d;
    if (e < E) { s = ei[e]; d = ei[E + e]; } else { s = d = e - E; }
    atomicAdd(&deg[d], 1.0f);
#pragma unroll
    for (int h = 0; h < 8; h++) {
        float l = lrelu(asrcn[s * 8 + h] + adstn[d * 8 + h]);
        atomicAdd(&den1[d * 8 + h], __expf(l));
    }
}

// ----- GAT1 weighted scatter: out1[dst] += alpha * h1[src]  (64 thr / edge) --
__global__ void k_scatter1(const int* __restrict__ ei, int E, int N,
                           const float* __restrict__ asrcn, const float* __restrict__ adstn,
                           const float* __restrict__ den1, const float* __restrict__ h1,
                           float* __restrict__ out1) {
    long long gtid = (long long)blockIdx.x * blockDim.x + threadIdx.x;
    int e = (int)(gtid >> 6);
    int q = (int)(gtid & 63);       // which float4 of 64
    int ET = E + N;
    if (e >= ET) return;
    int s, d;
    if (e < E) { s = ei[e]; d = ei[E + e]; } else { s = d = e - E; }
    int h = q >> 3;
    float l = lrelu(asrcn[s * 8 + h] + adstn[d * 8 + h]);
    float alpha = __expf(l) / den1[d * 8 + h];
    float4 hv = *reinterpret_cast<const float4*>(h1 + (size_t)s * 256 + q * 4);
    red_add_v4(out1 + (size_t)d * 256 + q * 4,
               hv.x * alpha, hv.y * alpha, hv.z * alpha, hv.w * alpha);
}

// ----- ELU with bias, in place -----------------------------------------------
__global__ void k_elu(float* __restrict__ buf, const float* __restrict__ b,
                      int total, int cmask) {
    int i = blockIdx.x * blockDim.x + threadIdx.x;
    if (i >= total) return;
    float v = buf[i] + b[i & cmask];
    buf[i] = v > 0.f ? v : expm1f(v);
}

// ----- GEMM2: h2 = x2[N,256] @ W2[256,16], fused alpha2 projections ----------
__global__ void k_gemm2(const float* __restrict__ x2, const float* __restrict__ W2,
                        const float* __restrict__ a_src2, const float* __restrict__ a_dst2,
                        float* __restrict__ h2, float* __restrict__ asrc2n,
                        float* __restrict__ adst2n, int N) {
    __shared__ float Wsh[256 * 16];
    int t = threadIdx.x;               // 256 threads -> 16 nodes x 16 cols
    for (int i = t; i < 4096; i += 256) Wsh[i] = W2[i];
    __syncthreads();
    int n = blockIdx.x * 16 + (t >> 4);
    int c = t & 15;
    if (n >= N) return;
    float acc = 0.f;
    const float4* xr = reinterpret_cast<const float4*>(x2 + (size_t)n * 256);
#pragma unroll 8
    for (int k4 = 0; k4 < 64; k4++) {
        float4 xv = xr[k4];
        acc += xv.x * Wsh[(k4 * 4 + 0) * 16 + c] + xv.y * Wsh[(k4 * 4 + 1) * 16 + c]
             + xv.z * Wsh[(k4 * 4 + 2) * 16 + c] + xv.w * Wsh[(k4 * 4 + 3) * 16 + c];
    }
    h2[(size_t)n * 16 + c] = acc;
    float r1 = acc * a_src2[c];
    float r2 = acc * a_dst2[c];
#pragma unroll
    for (int m = 8; m >= 1; m >>= 1) {
        r1 += __shfl_xor_sync(0xffffffffu, r1, m, 16);
        r2 += __shfl_xor_sync(0xffffffffu, r2, m, 16);
    }
    if (c == 0) { asrc2n[n] = r1; adst2n[n] = r2; }
}

// ----- GAT2 softmax denominator ----------------------------------------------
__global__ void k_den2(const int* __restrict__ ei, int E, int N,
                       const float* __restrict__ asrcn, const float* __restrict__ adstn,
                       float* __restrict__ den2) {
    int e = blockIdx.x * blockDim.x + threadIdx.x;
    int ET = E + N;
    if (e >= ET) return;
    int s, d;
    if (e < E) { s = ei[e]; d = ei[E + e]; } else { s = d = e - E; }
    float w = __expf(lrelu(asrcn[s] + adstn[d]));
    atomicAdd(&den2[d], w);
}

// ----- GAT2 weighted scatter (4 threads / edge) -------------------------------
__global__ void k_scatter2(const int* __restrict__ ei, int E, int N,
                           const float* __restrict__ asrcn, const float* __restrict__ adstn,
                           const float* __restrict__ den2, const float* __restrict__ h2,
                           float* __restrict__ out2) {
    long long gtid = (long long)blockIdx.x * blockDim.x + threadIdx.x;
    int e = (int)(gtid >> 2);
    int q = (int)(gtid & 3);
    int ET = E + N;
    if (e >= ET) return;
    int s, d;
    if (e < E) { s = ei[e]; d = ei[E + e]; } else { s = d = e - E; }
    float alpha = __expf(lrelu(asrcn[s] + adstn[d])) / den2[d];
    float4 hv = reinterpret_cast<const float4*>(h2 + (size_t)s * 16)[q];
    red_add_v4(out2 + (size_t)d * 16 + q * 4,
               hv.x * alpha, hv.y * alpha, hv.z * alpha, hv.w * alpha);
}

// ----- dinv = rsqrt(deg) -------------------------------------------------------
__global__ void k_dinv(const float* __restrict__ deg, float* __restrict__ dinv, int N) {
    int i = blockIdx.x * blockDim.x + threadIdx.x;
    if (i >= N) return;
    float dg = deg[i];
    dinv[i] = dg > 0.f ? rsqrtf(dg) : 0.f;
}

// ----- GCN transform: g = (x3 @ W3) * dinv[n] ---------------------------------
__global__ void k_h3(const float* __restrict__ x3, const float* __restrict__ W3,
                     const float* __restrict__ dinv, float* __restrict__ g, int N) {
    __shared__ float Wsh[256];
    if (threadIdx.x < 256) Wsh[threadIdx.x] = W3[threadIdx.x];
    __syncthreads();
    int n = blockIdx.x * blockDim.x + threadIdx.x;
    if (n >= N) return;
    float xr[16];
    const float4* xp = reinterpret_cast<const float4*>(x3 + (size_t)n * 16);
#pragma unroll
    for (int j = 0; j < 4; j++) {
        float4 v = xp[j];
        xr[4 * j + 0] = v.x; xr[4 * j + 1] = v.y; xr[4 * j + 2] = v.z; xr[4 * j + 3] = v.w;
    }
    float dv = dinv[n];
    float* go = g + (size_t)n * 16;
#pragma unroll
    for (int c = 0; c < 16; c++) {
        float acc = 0.f;
#pragma unroll
        for (int k = 0; k < 16; k++) acc += xr[k] * Wsh[k * 16 + c];
        go[c] = acc * dv;
    }
}

// ----- GCN scatter: out[dst] += g[src] (4 threads / edge) ----------------------
__global__ void k_scatter3(const int* __restrict__ ei, int E, int N,
                           const float* __restrict__ g, float* __restrict__ out) {
    long long gtid = (long long)blockIdx.x * blockDim.x + threadIdx.x;
    int e = (int)(gtid >> 2);
    int q = (int)(gtid & 3);
    int ET = E + N;
    if (e >= ET) return;
    int s, d;
    if (e < E) { s = ei[e]; d = ei[E + e]; } else { s = d = e - E; }
    float4 hv = reinterpret_cast<const float4*>(g + (size_t)s * 16)[q];
    red_add_v4(out + (size_t)d * 16 + q * 4, hv.x, hv.y, hv.z, hv.w);
}

// ----- finalize: out = out * dinv[dst] + b3 -----------------------------------
__global__ void k_final(float* __restrict__ out, const float* __restrict__ dinv,
                        const float* __restrict__ b3, int N) {
    int i = blockIdx.x * blockDim.x + threadIdx.x;
    if (i >= N * 16) return;
    out[i] = out[i] * dinv[i >> 4] + b3[i & 15];
}

// ---------------------------------------------------------------------------
extern "C" void kernel_launch(void* const* d_in, const int* in_sizes, int n_in,
                              void* d_out, int out_size) {
    const float* x      = (const float*)d_in[0];
    const int*   ei     = (const int*)d_in[1];
    const float* W1     = (const float*)d_in[2];
    const float* a_src1 = (const float*)d_in[3];
    const float* a_dst1 = (const float*)d_in[4];
    const float* b1     = (const float*)d_in[5];
    const float* W2     = (const float*)d_in[6];
    const float* a_src2 = (const float*)d_in[7];
    const float* a_dst2 = (const float*)d_in[8];
    const float* b2     = (const float*)d_in[9];
    const float* W3     = (const float*)d_in[10];
    const float* b3     = (const float*)d_in[11];
    float* out = (float*)d_out;

    const int N = in_sizes[0] / 128;
    const int E = in_sizes[1] / 2;
    const int ET = E + N;

    float *h1, *asrc1, *adst1, *den1, *out1, *h2, *asrc2, *adst2, *den2, *out2,
          *deg, *dinv, *g;
    void* p;
    cudaGetSymbolAddress(&p, g_h1);    h1    = (float*)p;
    cudaGetSymbolAddress(&p, g_asrc1); asrc1 = (float*)p;
    cudaGetSymbolAddress(&p, g_adst1); adst1 = (float*)p;
    cudaGetSymbolAddress(&p, g_den1);  den1  = (float*)p;
    cudaGetSymbolAddress(&p, g_out1);  out1  = (float*)p;
    cudaGetSymbolAddress(&p, g_h2);    h2    = (float*)p;
    cudaGetSymbolAddress(&p, g_asrc2); asrc2 = (float*)p;
    cudaGetSymbolAddress(&p, g_adst2); adst2 = (float*)p;
    cudaGetSymbolAddress(&p, g_den2);  den2  = (float*)p;
    cudaGetSymbolAddress(&p, g_out2);  out2  = (float*)p;
    cudaGetSymbolAddress(&p, g_deg);   deg   = (float*)p;
    cudaGetSymbolAddress(&p, g_dinv);  dinv  = (float*)p;
    cudaGetSymbolAddress(&p, g_g);     g     = (float*)p;

    // zero accumulators
    cudaMemsetAsync(den1, 0, (size_t)N * 8 * sizeof(float), 0);
    cudaMemsetAsync(out1, 0, (size_t)N * 256 * sizeof(float), 0);
    cudaMemsetAsync(den2, 0, (size_t)N * sizeof(float), 0);
    cudaMemsetAsync(out2, 0, (size_t)N * 16 * sizeof(float), 0);
    cudaMemsetAsync(deg,  0, (size_t)N * sizeof(float), 0);
    cudaMemsetAsync(out,  0, (size_t)N * 16 * sizeof(float), 0);

    const int B = 256;

    // Layer 1: GAT(128 -> 32 x 8 heads)
    k_gemm1<<<(N + 63) / 64, B>>>(x, W1, h1, N);
    k_alpha1<<<(N * 8 + B - 1) / B, B>>>(h1, a_src1, a_dst1, asrc1, adst1, N);
    k_den1<<<(ET + B - 1) / B, B>>>(ei, E, N, asrc1, adst1, den1, deg);
    {
        long long tot = (long long)ET * 64;
        k_scatter1<<<(unsigned)((tot + B - 1) / B), B>>>(ei, E, N, asrc1, adst1, den1, h1, out1);
    }
    k_elu<<<(N * 256 + B - 1) / B, B>>>(out1, b1, N * 256, 255);

    // Layer 2: GAT(256 -> 16, 1 head)
    k_gemm2<<<(N + 15) / 16, B>>>(out1, W2, a_src2, a_dst2, h2, asrc2, adst2, N);
    k_den2<<<(ET + B - 1) / B, B>>>(ei, E, N, asrc2, adst2, den2);
    {
        long long tot = (long long)ET * 4;
        k_scatter2<<<(unsigned)((tot + B - 1) / B), B>>>(ei, E, N, asrc2, adst2, den2, h2, out2);
    }
    k_elu<<<(N * 16 + B - 1) / B, B>>>(out2, b2, N * 16, 15);

    // Layer 3: GCN(16 -> 16)
    k_dinv<<<(N + B - 1) / B, B>>>(deg, dinv, N);
    k_h3<<<(N + B - 1) / B, B>>>(out2, W3, dinv, g, N);
    {
        long long tot = (long long)ET * 4;
        k_scatter3<<<(unsigned)((tot + B - 1) / B), B>>>(ei, E, N, g, out);
    }
    k_final<<<(N * 16 + B - 1) / B, B>>>(out, dinv, b3, N);
}

// round 2
// speedup vs baseline: 1.2163x; 1.2163x over previous
#include <cuda_runtime.h>
#include <math.h>

#define NMAX 50000
#define EMAX 800000

// ---------------- scratch (device globals; no allocation allowed) ------------
__device__ float g_h1[NMAX * 256];
__device__ float g_asrc1[NMAX * 8];
__device__ float g_adst1[NMAX * 8];
__device__ float g_den1[NMAX * 8];
__device__ float g_out1[NMAX * 256];
__device__ float g_h2[NMAX * 16];
__device__ float g_asrc2[NMAX];
__device__ float g_adst2[NMAX];
__device__ float g_den2[NMAX];
__device__ float g_out2[NMAX * 16];
__device__ float g_deg[NMAX];
__device__ float g_dinv[NMAX];
__device__ float g_g[NMAX * 16];

__device__ __forceinline__ float lrelu(float x) { return x > 0.f ? x : 0.2f * x; }

__device__ __forceinline__ void red_add_v4(float* p, float a, float b, float c, float d) {
    asm volatile("red.global.add.v4.f32 [%0], {%1,%2,%3,%4};"
                 :: "l"(p), "f"(a), "f"(b), "f"(c), "f"(d) : "memory");
}
__device__ __forceinline__ void red_add_f32(float* p, float a) {
    asm volatile("red.global.add.f32 [%0], %1;" :: "l"(p), "f"(a) : "memory");
}

// ---------------- GEMM1: h1 = x[N,128] @ W1[128,256] ------------------------
__global__ void k_gemm1(const float* __restrict__ x, const float* __restrict__ W1,
                        float* __restrict__ h1, int N) {
    __shared__ float xsT[128][68];
    const int t = threadIdx.x;               // 256 threads
    const int r0 = blockIdx.x * 64;
#pragma unroll
    for (int i = 0; i < 32; i++) {
        int lin = i * 256 + t;
        int r = lin >> 7, k = lin & 127;
        float v = (r0 + r < N) ? x[(size_t)(r0 + r) * 128 + k] : 0.f;
        xsT[k][r] = v;
    }
    __syncthreads();
    float acc[64];
#pragma unroll
    for (int i = 0; i < 64; i++) acc[i] = 0.f;
    const int col = t;
    for (int k = 0; k < 128; k++) {
        float w = W1[k * 256 + col];
        const float4* xr = reinterpret_cast<const float4*>(xsT[k]);
#pragma unroll
        for (int r4 = 0; r4 < 16; r4++) {
            float4 xv = xr[r4];
            acc[4 * r4 + 0] += xv.x * w;
            acc[4 * r4 + 1] += xv.y * w;
            acc[4 * r4 + 2] += xv.z * w;
            acc[4 * r4 + 3] += xv.w * w;
        }
    }
    for (int r = 0; r < 64; r++) {
        if (r0 + r < N) h1[(size_t)(r0 + r) * 256 + col] = acc[r];
    }
}

// ----- alpha projections for GAT1 -------------------------------------------
__global__ void k_alpha1(const float* __restrict__ h1, const float* __restrict__ a_src,
                         const float* __restrict__ a_dst, float* __restrict__ asrcn,
                         float* __restrict__ adstn, int N) {
    int i = blockIdx.x * blockDim.x + threadIdx.x;  // over N*8
    if (i >= N * 8) return;
    int h = i & 7;
    const float4* hp = reinterpret_cast<const float4*>(h1 + (size_t)i * 32);
    const float4* as = reinterpret_cast<const float4*>(a_src + h * 32);
    const float4* ad = reinterpret_cast<const float4*>(a_dst + h * 32);
    float s = 0.f, d = 0.f;
#pragma unroll
    for (int j = 0; j < 8; j++) {
        float4 hv = hp[j], av = as[j], dv = ad[j];
        s += hv.x * av.x + hv.y * av.y + hv.z * av.z + hv.w * av.w;
        d += hv.x * dv.x + hv.y * dv.y + hv.z * dv.z + hv.w * dv.w;
    }
    asrcn[i] = s;
    adstn[i] = d;
}

// ----- GAT1 softmax denominator + in-degree (vectorized) ---------------------
__global__ void k_den1(const int* __restrict__ ei, int E, int N,
                       const float* __restrict__ asrcn, const float* __restrict__ adstn,
                       float* __restrict__ den1, float* __restrict__ deg) {
    int e = blockIdx.x * blockDim.x + threadIdx.x;
    int ET = E + N;
    if (e >= ET) return;
    int s, d;
    if (e < E) { s = ei[e]; d = ei[E + e]; } else { s = d = e - E; }
    red_add_f32(&deg[d], 1.0f);
    const float4* sp = reinterpret_cast<const float4*>(asrcn + s * 8);
    const float4* dp = reinterpret_cast<const float4*>(adstn + d * 8);
    float4 s0 = sp[0], s1 = sp[1], d0 = dp[0], d1 = dp[1];
    float w0 = __expf(lrelu(s0.x + d0.x));
    float w1 = __expf(lrelu(s0.y + d0.y));
    float w2 = __expf(lrelu(s0.z + d0.z));
    float w3 = __expf(lrelu(s0.w + d0.w));
    float w4 = __expf(lrelu(s1.x + d1.x));
    float w5 = __expf(lrelu(s1.y + d1.y));
    float w6 = __expf(lrelu(s1.z + d1.z));
    float w7 = __expf(lrelu(s1.w + d1.w));
    red_add_v4(den1 + d * 8, w0, w1, w2, w3);
    red_add_v4(den1 + d * 8 + 4, w4, w5, w6, w7);
}

// ----- GAT1 weighted scatter: warp per edge ----------------------------------
__global__ void k_scatter1(const int* __restrict__ ei, int E, int N,
                           const float* __restrict__ asrcn, const float* __restrict__ adstn,
                           const float* __restrict__ den1, const float* __restrict__ h1,
                           float* __restrict__ out1) {
    int warp = (int)(((long long)blockIdx.x * blockDim.x + threadIdx.x) >> 5);
    int lane = threadIdx.x & 31;
    int ET = E + N;
    if (warp >= ET) return;
    int e = warp;
    int s = 0, d = 0;
    if (lane == 0) {
        if (e < E) { s = ei[e]; d = ei[E + e]; } else { s = d = e - E; }
    }
    s = __shfl_sync(0xffffffffu, s, 0);
    d = __shfl_sync(0xffffffffu, d, 0);
    float alpha = 0.f;
    if (lane < 8) {
        float l = lrelu(asrcn[s * 8 + lane] + adstn[d * 8 + lane]);
        alpha = __expf(l) / den1[d * 8 + lane];
    }
    int h0 = lane >> 3;                    // 0..3
    float a0 = __shfl_sync(0xffffffffu, alpha, h0);
    float a1 = __shfl_sync(0xffffffffu, alpha, h0 + 4);
    const float4* hp = reinterpret_cast<const float4*>(h1 + (size_t)s * 256);
    float4 v0 = hp[lane];
    float4 v1 = hp[lane + 32];
    float* op = out1 + (size_t)d * 256;
    red_add_v4(op + lane * 4, v0.x * a0, v0.y * a0, v0.z * a0, v0.w * a0);
    red_add_v4(op + 128 + lane * 4, v1.x * a1, v1.y * a1, v1.z * a1, v1.w * a1);
}

// ----- ELU with bias, float4, in place ---------------------------------------
__global__ void k_elu4(float* __restrict__ buf, const float* __restrict__ b,
                       int total4, int cmask4) {
    int i = blockIdx.x * blockDim.x + threadIdx.x;
    if (i >= total4) return;
    float4 v = reinterpret_cast<float4*>(buf)[i];
    float4 bb = reinterpret_cast<const float4*>(b)[i & cmask4];
    v.x += bb.x; v.y += bb.y; v.z += bb.z; v.w += bb.w;
    v.x = v.x > 0.f ? v.x : expm1f(v.x);
    v.y = v.y > 0.f ? v.y : expm1f(v.y);
    v.z = v.z > 0.f ? v.z : expm1f(v.z);
    v.w = v.w > 0.f ? v.w : expm1f(v.w);
    reinterpret_cast<float4*>(buf)[i] = v;
}

// ----- GEMM2: h2 = x2[N,256] @ W2[256,16], fused alpha2 ----------------------
__global__ void k_gemm2(const float* __restrict__ x2, const float* __restrict__ W2,
                        const float* __restrict__ a_src2, const float* __restrict__ a_dst2,
                        float* __restrict__ h2, float* __restrict__ asrc2n,
                        float* __restrict__ adst2n, int N) {
    __shared__ float Wsh[256 * 16];
    int t = threadIdx.x;               // 256 threads -> 16 nodes x 16 cols
    for (int i = t; i < 4096; i += 256) Wsh[i] = W2[i];
    __syncthreads();
    int n = blockIdx.x * 16 + (t >> 4);
    int c = t & 15;
    if (n >= N) return;
    float acc = 0.f;
    const float4* xr = reinterpret_cast<const float4*>(x2 + (size_t)n * 256);
#pragma unroll 8
    for (int k4 = 0; k4 < 64; k4++) {
        float4 xv = xr[k4];
        acc += xv.x * Wsh[(k4 * 4 + 0) * 16 + c] + xv.y * Wsh[(k4 * 4 + 1) * 16 + c]
             + xv.z * Wsh[(k4 * 4 + 2) * 16 + c] + xv.w * Wsh[(k4 * 4 + 3) * 16 + c];
    }
    h2[(size_t)n * 16 + c] = acc;
    float r1 = acc * a_src2[c];
    float r2 = acc * a_dst2[c];
#pragma unroll
    for (int m = 8; m >= 1; m >>= 1) {
        r1 += __shfl_xor_sync(0xffffffffu, r1, m, 16);
        r2 += __shfl_xor_sync(0xffffffffu, r2, m, 16);
    }
    if (c == 0) { asrc2n[n] = r1; adst2n[n] = r2; }
}

// ----- GAT2 softmax denominator ----------------------------------------------
__global__ void k_den2(const int* __restrict__ ei, int E, int N,
                       const float* __restrict__ asrcn, const float* __restrict__ adstn,
                       float* __restrict__ den2) {
    int e = blockIdx.x * blockDim.x + threadIdx.x;
    int ET = E + N;
    if (e >= ET) return;
    int s, d;
    if (e < E) { s = ei[e]; d = ei[E + e]; } else { s = d = e - E; }
    float w = __expf(lrelu(asrcn[s] + adstn[d]));
    red_add_f32(&den2[d], w);
}

// ----- GAT2 weighted scatter (4 threads / edge) -------------------------------
__global__ void k_scatter2(const int* __restrict__ ei, int E, int N,
                           const float* __restrict__ asrcn, const float* __restrict__ adstn,
                           const float* __restrict__ den2, const float* __restrict__ h2,
                           float* __restrict__ out2) {
    long long gtid = (long long)blockIdx.x * blockDim.x + threadIdx.x;
    int e = (int)(gtid >> 2);
    int q = (int)(gtid & 3);
    int ET = E + N;
    if (e >= ET) return;
    int s, d;
    if (e < E) { s = ei[e]; d = ei[E + e]; } else { s = d = e - E; }
    float alpha = __expf(lrelu(asrcn[s] + adstn[d])) / den2[d];
    float4 hv = reinterpret_cast<const float4*>(h2 + (size_t)s * 16)[q];
    red_add_v4(out2 + (size_t)d * 16 + q * 4,
               hv.x * alpha, hv.y * alpha, hv.z * alpha, hv.w * alpha);
}

// ----- dinv = rsqrt(deg) ------------------------------------------------------
__global__ void k_dinv(const float* __restrict__ deg, float* __restrict__ dinv, int N) {
    int i = blockIdx.x * blockDim.x + threadIdx.x;
    if (i >= N) return;
    float dg = deg[i];
    dinv[i] = dg > 0.f ? rsqrtf(dg) : 0.f;
}

// ----- GCN transform: g = (x3 @ W3) * dinv[n] ---------------------------------
__global__ void k_h3(const float* __restrict__ x3, const float* __restrict__ W3,
                     const float* __restrict__ dinv, float* __restrict__ g, int N) {
    __shared__ float Wsh[256];
    if (threadIdx.x < 256) Wsh[threadIdx.x] = W3[threadIdx.x];
    __syncthreads();
    int n = blockIdx.x * blockDim.x + threadIdx.x;
    if (n >= N) return;
    float xr[16];
    const float4* xp = reinterpret_cast<const float4*>(x3 + (size_t)n * 16);
#pragma unroll
    for (int j = 0; j < 4; j++) {
        float4 v = xp[j];
        xr[4 * j + 0] = v.x; xr[4 * j + 1] = v.y; xr[4 * j + 2] = v.z; xr[4 * j + 3] = v.w;
    }
    float dv = dinv[n];
    float* go = g + (size_t)n * 16;
#pragma unroll
    for (int c = 0; c < 16; c++) {
        float acc = 0.f;
#pragma unroll
        for (int k = 0; k < 16; k++) acc += xr[k] * Wsh[k * 16 + c];
        go[c] = acc * dv;
    }
}

// ----- GCN scatter: out[dst] += g[src] (4 threads / edge) ----------------------
__global__ void k_scatter3(const int* __restrict__ ei, int E, int N,
                           const float* __restrict__ g, float* __restrict__ out) {
    long long gtid = (long long)blockIdx.x * blockDim.x + threadIdx.x;
    int e = (int)(gtid >> 2);
    int q = (int)(gtid & 3);
    int ET = E + N;
    if (e >= ET) return;
    int s, d;
    if (e < E) { s = ei[e]; d = ei[E + e]; } else { s = d = e - E; }
    float4 hv = reinterpret_cast<const float4*>(g + (size_t)s * 16)[q];
    red_add_v4(out + (size_t)d * 16 + q * 4, hv.x, hv.y, hv.z, hv.w);
}

// ----- finalize: out = out * dinv[dst] + b3 -----------------------------------
__global__ void k_final(float* __restrict__ out, const float* __restrict__ dinv,
                        const float* __restrict__ b3, int N) {
    int i = blockIdx.x * blockDim.x + threadIdx.x;
    if (i >= N * 16) return;
    out[i] = out[i] * dinv[i >> 4] + b3[i & 15];
}

// ---------------------------------------------------------------------------
extern "C" void kernel_launch(void* const* d_in, const int* in_sizes, int n_in,
                              void* d_out, int out_size) {
    const float* x      = (const float*)d_in[0];
    const int*   ei     = (const int*)d_in[1];
    const float* W1     = (const float*)d_in[2];
    const float* a_src1 = (const float*)d_in[3];
    const float* a_dst1 = (const float*)d_in[4];
    const float* b1     = (const float*)d_in[5];
    const float* W2     = (const float*)d_in[6];
    const float* a_src2 = (const float*)d_in[7];
    const float* a_dst2 = (const float*)d_in[8];
    const float* b2     = (const float*)d_in[9];
    const float* W3     = (const float*)d_in[10];
    const float* b3     = (const float*)d_in[11];
    float* out = (float*)d_out;

    const int N = in_sizes[0] / 128;
    const int E = in_sizes[1] / 2;
    const int ET = E + N;

    float *h1, *asrc1, *adst1, *den1, *out1, *h2, *asrc2, *adst2, *den2, *out2,
          *deg, *dinv, *g;
    void* p;
    cudaGetSymbolAddress(&p, g_h1);    h1    = (float*)p;
    cudaGetSymbolAddress(&p, g_asrc1); asrc1 = (float*)p;
    cudaGetSymbolAddress(&p, g_adst1); adst1 = (float*)p;
    cudaGetSymbolAddress(&p, g_den1);  den1  = (float*)p;
    cudaGetSymbolAddress(&p, g_out1);  out1  = (float*)p;
    cudaGetSymbolAddress(&p, g_h2);    h2    = (float*)p;
    cudaGetSymbolAddress(&p, g_asrc2); asrc2 = (float*)p;
    cudaGetSymbolAddress(&p, g_adst2); adst2 = (float*)p;
    cudaGetSymbolAddress(&p, g_den2);  den2  = (float*)p;
    cudaGetSymbolAddress(&p, g_out2);  out2  = (float*)p;
    cudaGetSymbolAddress(&p, g_deg);   deg   = (float*)p;
    cudaGetSymbolAddress(&p, g_dinv);  dinv  = (float*)p;
    cudaGetSymbolAddress(&p, g_g);     g     = (float*)p;

    // zero accumulators
    cudaMemsetAsync(den1, 0, (size_t)N * 8 * sizeof(float), 0);
    cudaMemsetAsync(out1, 0, (size_t)N * 256 * sizeof(float), 0);
    cudaMemsetAsync(den2, 0, (size_t)N * sizeof(float), 0);
    cudaMemsetAsync(out2, 0, (size_t)N * 16 * sizeof(float), 0);
    cudaMemsetAsync(deg,  0, (size_t)N * sizeof(float), 0);
    cudaMemsetAsync(out,  0, (size_t)N * 16 * sizeof(float), 0);

    const int B = 256;

    // Layer 1: GAT(128 -> 32 x 8 heads)
    k_gemm1<<<(N + 63) / 64, B>>>(x, W1, h1, N);
    k_alpha1<<<(N * 8 + B - 1) / B, B>>>(h1, a_src1, a_dst1, asrc1, adst1, N);
    k_den1<<<(ET + B - 1) / B, B>>>(ei, E, N, asrc1, adst1, den1, deg);
    {
        long long tot = (long long)ET * 32;   // warp per edge
        k_scatter1<<<(unsigned)((tot + B - 1) / B), B>>>(ei, E, N, asrc1, adst1, den1, h1, out1);
    }
    k_elu4<<<(N * 64 + B - 1) / B, B>>>(out1, b1, N * 64, 63);

    // Layer 2: GAT(256 -> 16, 1 head)
    k_gemm2<<<(N + 15) / 16, B>>>(out1, W2, a_src2, a_dst2, h2, asrc2, adst2, N);
    k_den2<<<(ET + B - 1) / B, B>>>(ei, E, N, asrc2, adst2, den2);
    {
        long long tot = (long long)ET * 4;
        k_scatter2<<<(unsigned)((tot + B - 1) / B), B>>>(ei, E, N, asrc2, adst2, den2, h2, out2);
    }
    k_elu4<<<(N * 4 + B - 1) / B, B>>>(out2, b2, N * 4, 3);

    // Layer 3: GCN(16 -> 16)
    k_dinv<<<(N + B - 1) / B, B>>>(deg, dinv, N);
    k_h3<<<(N + B - 1) / B, B>>>(out2, W3, dinv, g, N);
    {
        long long tot = (long long)ET * 4;
        k_scatter3<<<(unsigned)((tot + B - 1) / B), B>>>(ei, E, N, g, out);
    }
    k_final<<<(N * 16 + B - 1) / B, B>>>(out, dinv, b3, N);
}

// round 3
// speedup vs baseline: 1.5401x; 1.2663x over previous
#include <cuda_runtime.h>
#include <math.h>

#define NMAX 50000
#define EMAX 800000
#define ETMAX (EMAX + NMAX)

// ---------------- scratch (device globals) -----------------------------------
__device__ float g_h1[NMAX * 256];
__device__ float g_asrc1[NMAX * 8];
__device__ float g_adst1[NMAX * 8];
__device__ float g_out1[NMAX * 256];
__device__ float g_h2[NMAX * 16];
__device__ float g_asrc2[NMAX];
__device__ float g_adst2[NMAX];
__device__ float g_out2[NMAX * 16];
__device__ float g_g[NMAX * 16];
__device__ int   g_degi[NMAX];
__device__ int   g_cursor[NMAX];
__device__ int   g_rowptr[NMAX + 1];
__device__ int   g_esrc[ETMAX];

__device__ __forceinline__ float lrelu(float x) { return x > 0.f ? x : 0.2f * x; }
__device__ __forceinline__ float eluf(float x) { return x > 0.f ? x : expm1f(x); }

// ---------------- CSR build ---------------------------------------------------
__global__ void k_deg(const int* __restrict__ ei, int E, int N, int* __restrict__ degi) {
    int e = blockIdx.x * blockDim.x + threadIdx.x;
    int ET = E + N;
    if (e >= ET) return;
    int d = (e < E) ? ei[E + e] : e - E;
    atomicAdd(&degi[d], 1);
}

__global__ void k_scan(const int* __restrict__ degi, int* __restrict__ rowptr,
                       int N, int ET) {
    __shared__ int sh[1024];
    int t = threadIdx.x;
    int chunk = (N + 1023) / 1024;
    int start = t * chunk;
    int end = min(start + chunk, N);
    int sum = 0;
    for (int i = start; i < end; i++) sum += degi[i];
    sh[t] = sum;
    __syncthreads();
    for (int off = 1; off < 1024; off <<= 1) {
        int v = (t >= off) ? sh[t - off] : 0;
        __syncthreads();
        sh[t] += v;
        __syncthreads();
    }
    int run = (t == 0) ? 0 : sh[t - 1];
    for (int i = start; i < end; i++) { rowptr[i] = run; run += degi[i]; }
    if (t == 1023) rowptr[N] = ET;
}

__global__ void k_fill(const int* __restrict__ ei, int E, int N,
                       const int* __restrict__ rowptr, int* __restrict__ cursor,
                       int* __restrict__ esrc) {
    int e = blockIdx.x * blockDim.x + threadIdx.x;
    int ET = E + N;
    if (e >= ET) return;
    int s, d;
    if (e < E) { s = ei[e]; d = ei[E + e]; } else { s = d = e - E; }
    int pos = rowptr[d] + atomicAdd(&cursor[d], 1);
    esrc[pos] = s;
}

// ---------------- GEMM1: h1 = x[N,128] @ W1[128,256] -------------------------
__global__ void k_gemm1(const float* __restrict__ x, const float* __restrict__ W1,
                        float* __restrict__ h1, int N) {
    __shared__ float xsT[128][68];
    const int t = threadIdx.x;               // 256 threads
    const int r0 = blockIdx.x * 64;
#pragma unroll
    for (int i = 0; i < 32; i++) {
        int lin = i * 256 + t;
        int r = lin >> 7, k = lin & 127;
        float v = (r0 + r < N) ? x[(size_t)(r0 + r) * 128 + k] : 0.f;
        xsT[k][r] = v;
    }
    __syncthreads();
    float acc[64];
#pragma unroll
    for (int i = 0; i < 64; i++) acc[i] = 0.f;
    const int col = t;
    for (int k = 0; k < 128; k++) {
        float w = W1[k * 256 + col];
        const float4* xr = reinterpret_cast<const float4*>(xsT[k]);
#pragma unroll
        for (int r4 = 0; r4 < 16; r4++) {
            float4 xv = xr[r4];
            acc[4 * r4 + 0] += xv.x * w;
            acc[4 * r4 + 1] += xv.y * w;
            acc[4 * r4 + 2] += xv.z * w;
            acc[4 * r4 + 3] += xv.w * w;
        }
    }
    for (int r = 0; r < 64; r++) {
        if (r0 + r < N) h1[(size_t)(r0 + r) * 256 + col] = acc[r];
    }
}

// ----- alpha projections for GAT1 --------------------------------------------
__global__ void k_alpha1(const float* __restrict__ h1, const float* __restrict__ a_src,
                         const float* __restrict__ a_dst, float* __restrict__ asrcn,
                         float* __restrict__ adstn, int N) {
    int i = blockIdx.x * blockDim.x + threadIdx.x;  // over N*8
    if (i >= N * 8) return;
    int h = i & 7;
    const float4* hp = reinterpret_cast<const float4*>(h1 + (size_t)i * 32);
    const float4* as = reinterpret_cast<const float4*>(a_src + h * 32);
    const float4* ad = reinterpret_cast<const float4*>(a_dst + h * 32);
    float s = 0.f, d = 0.f;
#pragma unroll
    for (int j = 0; j < 8; j++) {
        float4 hv = hp[j], av = as[j], dv = ad[j];
        s += hv.x * av.x + hv.y * av.y + hv.z * av.z + hv.w * av.w;
        d += hv.x * dv.x + hv.y * dv.y + hv.z * dv.z + hv.w * dv.w;
    }
    asrcn[i] = s;
    adstn[i] = d;
}

// ----- GAT1 pull aggregation: warp per dst, fused softmax+bias+ELU -----------
__global__ void k_agg1(const int* __restrict__ rowptr, const int* __restrict__ esrc,
                       const float* __restrict__ asrc, const float* __restrict__ adst,
                       const float* __restrict__ h1, const float* __restrict__ b1,
                       float* __restrict__ out1, int N) {
    int d = (int)(((long long)blockIdx.x * blockDim.x + threadIdx.x) >> 5);
    int lane = threadIdx.x & 31;
    if (d >= N) return;
    int beg = rowptr[d], endp = rowptr[d + 1];
    float ad = (lane < 8) ? adst[d * 8 + lane] : 0.f;
    float den = 0.f;
    float4 acc0 = {0, 0, 0, 0}, acc1 = {0, 0, 0, 0};
    int h0 = lane >> 3;
    for (int base = beg; base < endp; base += 32) {
        int nn = min(32, endp - base);
        int sreg = (base + lane < endp) ? esrc[base + lane] : 0;
        for (int j = 0; j < nn; j++) {
            int s = __shfl_sync(0xffffffffu, sreg, j);
            float wgt = 0.f;
            if (lane < 8) wgt = __expf(lrelu(asrc[s * 8 + lane] + ad));
            den += wgt;
            float a0 = __shfl_sync(0xffffffffu, wgt, h0);
            float a1 = __shfl_sync(0xffffffffu, wgt, h0 + 4);
            const float4* hp = reinterpret_cast<const float4*>(h1 + (size_t)s * 256);
            float4 v0 = hp[lane];
            float4 v1 = hp[lane + 32];
            acc0.x += v0.x * a0; acc0.y += v0.y * a0; acc0.z += v0.z * a0; acc0.w += v0.w * a0;
            acc1.x += v1.x * a1; acc1.y += v1.y * a1; acc1.z += v1.z * a1; acc1.w += v1.w * a1;
        }
    }
    float dn0 = __shfl_sync(0xffffffffu, den, h0);
    float dn1 = __shfl_sync(0xffffffffu, den, h0 + 4);
    float r0 = 1.f / dn0, r1 = 1.f / dn1;
    const float4* bp = reinterpret_cast<const float4*>(b1);
    float4 bb0 = bp[lane], bb1 = bp[lane + 32];
    float4 o0, o1;
    o0.x = eluf(acc0.x * r0 + bb0.x); o0.y = eluf(acc0.y * r0 + bb0.y);
    o0.z = eluf(acc0.z * r0 + bb0.z); o0.w = eluf(acc0.w * r0 + bb0.w);
    o1.x = eluf(acc1.x * r1 + bb1.x); o1.y = eluf(acc1.y * r1 + bb1.y);
    o1.z = eluf(acc1.z * r1 + bb1.z); o1.w = eluf(acc1.w * r1 + bb1.w);
    float4* op = reinterpret_cast<float4*>(out1 + (size_t)d * 256);
    op[lane] = o0;
    op[lane + 32] = o1;
}

// ----- GEMM2: h2 = x2[N,256] @ W2[256,16], fused alpha2 ----------------------
__global__ void k_gemm2(const float* __restrict__ x2, const float* __restrict__ W2,
                        const float* __restrict__ a_src2, const float* __restrict__ a_dst2,
                        float* __restrict__ h2, float* __restrict__ asrc2n,
                        float* __restrict__ adst2n, int N) {
    __shared__ float Wsh[256 * 16];
    int t = threadIdx.x;               // 256 threads -> 16 nodes x 16 cols
    for (int i = t; i < 4096; i += 256) Wsh[i] = W2[i];
    __syncthreads();
    int n = blockIdx.x * 16 + (t >> 4);
    int c = t & 15;
    if (n >= N) return;
    float acc = 0.f;
    const float4* xr = reinterpret_cast<const float4*>(x2 + (size_t)n * 256);
#pragma unroll 8
    for (int k4 = 0; k4 < 64; k4++) {
        float4 xv = xr[k4];
        acc += xv.x * Wsh[(k4 * 4 + 0) * 16 + c] + xv.y * Wsh[(k4 * 4 + 1) * 16 + c]
             + xv.z * Wsh[(k4 * 4 + 2) * 16 + c] + xv.w * Wsh[(k4 * 4 + 3) * 16 + c];
    }
    h2[(size_t)n * 16 + c] = acc;
    float r1 = acc * a_src2[c];
    float r2 = acc * a_dst2[c];
#pragma unroll
    for (int m = 8; m >= 1; m >>= 1) {
        r1 += __shfl_xor_sync(0xffffffffu, r1, m, 16);
        r2 += __shfl_xor_sync(0xffffffffu, r2, m, 16);
    }
    if (c == 0) { asrc2n[n] = r1; adst2n[n] = r2; }
}

// ----- GAT2 pull aggregation: 4 lanes per dst, fused softmax+bias+ELU --------
__global__ void k_agg2(const int* __restrict__ rowptr, const int* __restrict__ esrc,
                       const float* __restrict__ asrc, const float* __restrict__ adst,
                       const float* __restrict__ h2, const float* __restrict__ b2,
                       float* __restrict__ out2, int N) {
    long long gt = (long long)blockIdx.x * blockDim.x + threadIdx.x;
    int d = (int)(gt >> 2);
    int q = threadIdx.x & 3;
    if (d >= N) return;
    int beg = rowptr[d], endp = rowptr[d + 1];
    float ad = adst[d];
    float den = 0.f;
    float4 acc = {0, 0, 0, 0};
    for (int idx = beg; idx < endp; idx++) {
        int s = esrc[idx];
        float wgt = __expf(lrelu(asrc[s] + ad));
        den += wgt;
        float4 v = reinterpret_cast<const float4*>(h2 + (size_t)s * 16)[q];
        acc.x += v.x * wgt; acc.y += v.y * wgt; acc.z += v.z * wgt; acc.w += v.w * wgt;
    }
    float r = 1.f / den;
    float4 bb = reinterpret_cast<const float4*>(b2)[q];
    float4 o;
    o.x = eluf(acc.x * r + bb.x); o.y = eluf(acc.y * r + bb.y);
    o.z = eluf(acc.z * r + bb.z); o.w = eluf(acc.w * r + bb.w);
    reinterpret_cast<float4*>(out2 + (size_t)d * 16)[q] = o;
}

// ----- GCN transform: g = (x3 @ W3) * dinv[n], dinv from rowptr ---------------
__global__ void k_h3(const float* __restrict__ x3, const float* __restrict__ W3,
                     const int* __restrict__ rowptr, float* __restrict__ g, int N) {
    __shared__ float Wsh[256];
    if (threadIdx.x < 256) Wsh[threadIdx.x] = W3[threadIdx.x];
    __syncthreads();
    int n = blockIdx.x * blockDim.x + threadIdx.x;
    if (n >= N) return;
    float xr[16];
    const float4* xp = reinterpret_cast<const float4*>(x3 + (size_t)n * 16);
#pragma unroll
    for (int j = 0; j < 4; j++) {
        float4 v = xp[j];
        xr[4 * j + 0] = v.x; xr[4 * j + 1] = v.y; xr[4 * j + 2] = v.z; xr[4 * j + 3] = v.w;
    }
    float dv = rsqrtf((float)(rowptr[n + 1] - rowptr[n]));
    float* go = g + (size_t)n * 16;
#pragma unroll
    for (int c = 0; c < 16; c++) {
        float acc = 0.f;
#pragma unroll
        for (int k = 0; k < 16; k++) acc += xr[k] * Wsh[k * 16 + c];
        go[c] = acc * dv;
    }
}

// ----- GCN pull aggregation + finalize: 4 lanes per dst ----------------------
__global__ void k_agg3(const int* __restrict__ rowptr, const int* __restrict__ esrc,
                       const float* __restrict__ g, const float* __restrict__ b3,
                       float* __restrict__ out, int N) {
    long long gt = (long long)blockIdx.x * blockDim.x + threadIdx.x;
    int d = (int)(gt >> 2);
    int q = threadIdx.x & 3;
    if (d >= N) return;
    int beg = rowptr[d], endp = rowptr[d + 1];
    float4 acc = {0, 0, 0, 0};
    for (int idx = beg; idx < endp; idx++) {
        int s = esrc[idx];
        float4 v = reinterpret_cast<const float4*>(g + (size_t)s * 16)[q];
        acc.x += v.x; acc.y += v.y; acc.z += v.z; acc.w += v.w;
    }
    float dv = rsqrtf((float)(endp - beg));
    float4 bb = reinterpret_cast<const float4*>(b3)[q];
    float4 o;
    o.x = acc.x * dv + bb.x; o.y = acc.y * dv + bb.y;
    o.z = acc.z * dv + bb.z; o.w = acc.w * dv + bb.w;
    reinterpret_cast<float4*>(out + (size_t)d * 16)[q] = o;
}

// ---------------------------------------------------------------------------
extern "C" void kernel_launch(void* const* d_in, const int* in_sizes, int n_in,
                              void* d_out, int out_size) {
    const float* x      = (const float*)d_in[0];
    const int*   ei     = (const int*)d_in[1];
    const float* W1     = (const float*)d_in[2];
    const float* a_src1 = (const float*)d_in[3];
    const float* a_dst1 = (const float*)d_in[4];
    const float* b1     = (const float*)d_in[5];
    const float* W2     = (const float*)d_in[6];
    const float* a_src2 = (const float*)d_in[7];
    const float* a_dst2 = (const float*)d_in[8];
    const float* b2     = (const float*)d_in[9];
    const float* W3     = (const float*)d_in[10];
    const float* b3     = (const float*)d_in[11];
    float* out = (float*)d_out;

    const int N = in_sizes[0] / 128;
    const int E = in_sizes[1] / 2;
    const int ET = E + N;

    float *h1, *asrc1, *adst1, *out1, *h2, *asrc2, *adst2, *out2, *g;
    int *degi, *cursor, *rowptr, *esrc;
    void* p;
    cudaGetSymbolAddress(&p, g_h1);     h1     = (float*)p;
    cudaGetSymbolAddress(&p, g_asrc1);  asrc1  = (float*)p;
    cudaGetSymbolAddress(&p, g_adst1);  adst1  = (float*)p;
    cudaGetSymbolAddress(&p, g_out1);   out1   = (float*)p;
    cudaGetSymbolAddress(&p, g_h2);     h2     = (float*)p;
    cudaGetSymbolAddress(&p, g_asrc2);  asrc2  = (float*)p;
    cudaGetSymbolAddress(&p, g_adst2);  adst2  = (float*)p;
    cudaGetSymbolAddress(&p, g_out2);   out2   = (float*)p;
    cudaGetSymbolAddress(&p, g_g);      g      = (float*)p;
    cudaGetSymbolAddress(&p, g_degi);   degi   = (int*)p;
    cudaGetSymbolAddress(&p, g_cursor); cursor = (int*)p;
    cudaGetSymbolAddress(&p, g_rowptr); rowptr = (int*)p;
    cudaGetSymbolAddress(&p, g_esrc);   esrc   = (int*)p;

    cudaMemsetAsync(degi,   0, (size_t)N * sizeof(int), 0);
    cudaMemsetAsync(cursor, 0, (size_t)N * sizeof(int), 0);

    const int B = 256;

    // CSR build (shared by all three layers)
    k_deg<<<(ET + B - 1) / B, B>>>(ei, E, N, degi);
    k_scan<<<1, 1024>>>(degi, rowptr, N, ET);
    k_fill<<<(ET + B - 1) / B, B>>>(ei, E, N, rowptr, cursor, esrc);

    // Layer 1: GAT(128 -> 32 x 8 heads)
    k_gemm1<<<(N + 63) / 64, B>>>(x, W1, h1, N);
    k_alpha1<<<(N * 8 + B - 1) / B, B>>>(h1, a_src1, a_dst1, asrc1, adst1, N);
    {
        long long tot = (long long)N * 32;   // warp per dst
        k_agg1<<<(unsigned)((tot + B - 1) / B), B>>>(rowptr, esrc, asrc1, adst1, h1, b1, out1, N);
    }

    // Layer 2: GAT(256 -> 16, 1 head)
    k_gemm2<<<(N + 15) / 16, B>>>(out1, W2, a_src2, a_dst2, h2, asrc2, adst2, N);
    {
        long long tot = (long long)N * 4;
        k_agg2<<<(unsigned)((tot + B - 1) / B), B>>>(rowptr, esrc, asrc2, adst2, h2, b2, out2, N);
    }

    // Layer 3: GCN(16 -> 16)
    k_h3<<<(N + B - 1) / B, B>>>(out2, W3, rowptr, g, N);
    {
        long long tot = (long long)N * 4;
        k_agg3<<<(unsigned)((tot + B - 1) / B), B>>>(rowptr, esrc, g, b3, out, N);
    }
}

// round 4
// speedup vs baseline: 1.6964x; 1.1015x over previous
#include <cuda_runtime.h>
#include <math.h>

#define NMAX 50000
#define EMAX 800000
#define ETMAX (EMAX + NMAX)

// ---------------- scratch (device globals) -----------------------------------
__device__ float g_h1[NMAX * 256];
__device__ float g_asrc1[NMAX * 8];
__device__ float g_adst1[NMAX * 8];
__device__ float g_out1[NMAX * 256];
__device__ float g_h2[NMAX * 16];
__device__ float g_asrc2[NMAX];
__device__ float g_adst2[NMAX];
__device__ float g_out2[NMAX * 16];
__device__ float g_g[NMAX * 16];
__device__ int   g_degi[NMAX];
__device__ int   g_cursor[NMAX];
__device__ int   g_rowptr[NMAX + 1];
__device__ int   g_esrc[ETMAX];

__device__ __forceinline__ float lrelu(float x) { return x > 0.f ? x : 0.2f * x; }
__device__ __forceinline__ float eluf(float x) { return x > 0.f ? x : expm1f(x); }

// ---------------- CSR build ---------------------------------------------------
__global__ void k_deg(const int* __restrict__ ei, int E, int N, int* __restrict__ degi) {
    int e = blockIdx.x * blockDim.x + threadIdx.x;
    int ET = E + N;
    if (e >= ET) return;
    int d = (e < E) ? ei[E + e] : e - E;
    atomicAdd(&degi[d], 1);
}

__global__ void k_scan(const int* __restrict__ degi, int* __restrict__ rowptr,
                       int N, int ET) {
    __shared__ int sh[1024];
    int t = threadIdx.x;
    int chunk = (N + 1023) / 1024;
    int start = t * chunk;
    int end = min(start + chunk, N);
    int sum = 0;
    for (int i = start; i < end; i++) sum += degi[i];
    sh[t] = sum;
    __syncthreads();
    for (int off = 1; off < 1024; off <<= 1) {
        int v = (t >= off) ? sh[t - off] : 0;
        __syncthreads();
        sh[t] += v;
        __syncthreads();
    }
    int run = (t == 0) ? 0 : sh[t - 1];
    for (int i = start; i < end; i++) { rowptr[i] = run; run += degi[i]; }
    if (t == 1023) rowptr[N] = ET;
}

__global__ void k_fill(const int* __restrict__ ei, int E, int N,
                       const int* __restrict__ rowptr, int* __restrict__ cursor,
                       int* __restrict__ esrc) {
    int e = blockIdx.x * blockDim.x + threadIdx.x;
    int ET = E + N;
    if (e >= ET) return;
    int s, d;
    if (e < E) { s = ei[e]; d = ei[E + e]; } else { s = d = e - E; }
    int pos = rowptr[d] + atomicAdd(&cursor[d], 1);
    esrc[pos] = s;
}

// ---------------- tf32 helpers ------------------------------------------------
__device__ __forceinline__ void tf32split(float x, float& hi, float& lo) {
    unsigned u;
    asm("cvt.rna.tf32.f32 %0, %1;" : "=r"(u) : "f"(x));
    hi = __uint_as_float(u);
    float r = x - hi;
    unsigned ul;
    asm("cvt.rna.tf32.f32 %0, %1;" : "=r"(ul) : "f"(r));
    lo = __uint_as_float(ul);
}

__device__ __forceinline__ void mma_tf32(float* d, const unsigned* a, const unsigned* b) {
    asm volatile("mma.sync.aligned.m16n8k8.row.col.f32.tf32.tf32.f32 "
                 "{%0,%1,%2,%3}, {%4,%5,%6,%7}, {%8,%9}, {%0,%1,%2,%3};"
                 : "+f"(d[0]), "+f"(d[1]), "+f"(d[2]), "+f"(d[3])
                 : "r"(a[0]), "r"(a[1]), "r"(a[2]), "r"(a[3]),
                   "r"(b[0]), "r"(b[1]));
}

// ---------------- GEMM1 (tensor core, split-tf32): h1 = x @ W1 ----------------
// block: 64 rows x 128 cols, 8 warps (2x4), warp tile 32x32
__global__ __launch_bounds__(256) void k_gemm1_tc(
        const float* __restrict__ x, const float* __restrict__ W1,
        float* __restrict__ h1, int N) {
    __shared__ float xs_hi[64][20], xs_lo[64][20];     // [m][k], pad 20
    __shared__ float ws_hi[16][136], ws_lo[16][136];   // [k][n], pad 136

    const int t = threadIdx.x;
    const int warp = t >> 5, lane = t & 31;
    const int wm = warp >> 2, wn = warp & 3;           // wm 0..1, wn 0..3
    const int lm = lane >> 2, lk = lane & 3;           // lm 0..7, lk 0..3
    const int r0 = blockIdx.x * 64;
    const int n0 = blockIdx.y * 128;

    float acc[2][4][4];
#pragma unroll
    for (int i = 0; i < 2; i++)
#pragma unroll
        for (int j = 0; j < 4; j++)
#pragma unroll
            for (int v = 0; v < 4; v++) acc[i][j][v] = 0.f;

    for (int k0 = 0; k0 < 128; k0 += 16) {
        // ---- load x tile 64x16 ----
        {
            int m = t >> 2, kq = (t & 3) * 4;
            float4 v = make_float4(0.f, 0.f, 0.f, 0.f);
            if (r0 + m < N)
                v = *reinterpret_cast<const float4*>(x + (size_t)(r0 + m) * 128 + k0 + kq);
            float h, l;
            tf32split(v.x, h, l); xs_hi[m][kq + 0] = h; xs_lo[m][kq + 0] = l;
            tf32split(v.y, h, l); xs_hi[m][kq + 1] = h; xs_lo[m][kq + 1] = l;
            tf32split(v.z, h, l); xs_hi[m][kq + 2] = h; xs_lo[m][kq + 2] = l;
            tf32split(v.w, h, l); xs_hi[m][kq + 3] = h; xs_lo[m][kq + 3] = l;
        }
        // ---- load W tile 16x128 ----
        {
            int kk = t >> 4, nb = (t & 15) * 8;
            const float* wp = W1 + (size_t)(k0 + kk) * 256 + n0 + nb;
            float4 v0 = *reinterpret_cast<const float4*>(wp);
            float4 v1 = *reinterpret_cast<const float4*>(wp + 4);
            float h, l;
            tf32split(v0.x, h, l); ws_hi[kk][nb + 0] = h; ws_lo[kk][nb + 0] = l;
            tf32split(v0.y, h, l); ws_hi[kk][nb + 1] = h; ws_lo[kk][nb + 1] = l;
            tf32split(v0.z, h, l); ws_hi[kk][nb + 2] = h; ws_lo[kk][nb + 2] = l;
            tf32split(v0.w, h, l); ws_hi[kk][nb + 3] = h; ws_lo[kk][nb + 3] = l;
            tf32split(v1.x, h, l); ws_hi[kk][nb + 4] = h; ws_lo[kk][nb + 4] = l;
            tf32split(v1.y, h, l); ws_hi[kk][nb + 5] = h; ws_lo[kk][nb + 5] = l;
            tf32split(v1.z, h, l); ws_hi[kk][nb + 6] = h; ws_lo[kk][nb + 6] = l;
            tf32split(v1.w, h, l); ws_hi[kk][nb + 7] = h; ws_lo[kk][nb + 7] = l;
        }
        __syncthreads();

#pragma unroll
        for (int ks = 0; ks < 16; ks += 8) {
            unsigned Ah[2][4], Al[2][4];
#pragma unroll
            for (int mt = 0; mt < 2; mt++) {
                int mb = wm * 32 + mt * 16;
                int c1 = ks + lk, c2 = ks + lk + 4;
                Ah[mt][0] = __float_as_uint(xs_hi[mb + lm][c1]);
                Ah[mt][1] = __float_as_uint(xs_hi[mb + lm + 8][c1]);
                Ah[mt][2] = __float_as_uint(xs_hi[mb + lm][c2]);
                Ah[mt][3] = __float_as_uint(xs_hi[mb + lm + 8][c2]);
                Al[mt][0] = __float_as_uint(xs_lo[mb + lm][c1]);
                Al[mt][1] = __float_as_uint(xs_lo[mb + lm + 8][c1]);
                Al[mt][2] = __float_as_uint(xs_lo[mb + lm][c2]);
                Al[mt][3] = __float_as_uint(xs_lo[mb + lm + 8][c2]);
            }
            unsigned Bh[4][2], Bl[4][2];
#pragma unroll
            for (int nt = 0; nt < 4; nt++) {
                int nb = wn * 32 + nt * 8 + lm;
                Bh[nt][0] = __float_as_uint(ws_hi[ks + lk][nb]);
                Bh[nt][1] = __float_as_uint(ws_hi[ks + lk + 4][nb]);
                Bl[nt][0] = __float_as_uint(ws_lo[ks + lk][nb]);
                Bl[nt][1] = __float_as_uint(ws_lo[ks + lk + 4][nb]);
            }
#pragma unroll
            for (int mt = 0; mt < 2; mt++)
#pragma unroll
                for (int nt = 0; nt < 4; nt++) {
                    mma_tf32(acc[mt][nt], Ah[mt], Bh[nt]);
                    mma_tf32(acc[mt][nt], Ah[mt], Bl[nt]);
                    mma_tf32(acc[mt][nt], Al[mt], Bh[nt]);
                }
        }
        __syncthreads();
    }

    // epilogue
#pragma unroll
    for (int mt = 0; mt < 2; mt++) {
        int row1 = r0 + wm * 32 + mt * 16 + lm;
        int row2 = row1 + 8;
#pragma unroll
        for (int nt = 0; nt < 4; nt++) {
            int col = n0 + wn * 32 + nt * 8 + lk * 2;
            if (row1 < N) {
                float2 v = make_float2(acc[mt][nt][0], acc[mt][nt][1]);
                *reinterpret_cast<float2*>(h1 + (size_t)row1 * 256 + col) = v;
            }
            if (row2 < N) {
                float2 v = make_float2(acc[mt][nt][2], acc[mt][nt][3]);
                *reinterpret_cast<float2*>(h1 + (size_t)row2 * 256 + col) = v;
            }
        }
    }
}

// ----- alpha projections for GAT1 --------------------------------------------
__global__ void k_alpha1(const float* __restrict__ h1, const float* __restrict__ a_src,
                         const float* __restrict__ a_dst, float* __restrict__ asrcn,
                         float* __restrict__ adstn, int N) {
    int i = blockIdx.x * blockDim.x + threadIdx.x;  // over N*8
    if (i >= N * 8) return;
    int h = i & 7;
    const float4* hp = reinterpret_cast<const float4*>(h1 + (size_t)i * 32);
    const float4* as = reinterpret_cast<const float4*>(a_src + h * 32);
    const float4* ad = reinterpret_cast<const float4*>(a_dst + h * 32);
    float s = 0.f, d = 0.f;
#pragma unroll
    for (int j = 0; j < 8; j++) {
        float4 hv = hp[j], av = as[j], dv = ad[j];
        s += hv.x * av.x + hv.y * av.y + hv.z * av.z + hv.w * av.w;
        d += hv.x * dv.x + hv.y * dv.y + hv.z * dv.z + hv.w * dv.w;
    }
    asrcn[i] = s;
    adstn[i] = d;
}

// ----- GAT1 pull aggregation: warp per dst, fused softmax+bias+ELU -----------
__global__ void k_agg1(const int* __restrict__ rowptr, const int* __restrict__ esrc,
                       const float* __restrict__ asrc, const float* __restrict__ adst,
                       const float* __restrict__ h1, const float* __restrict__ b1,
                       float* __restrict__ out1, int N) {
    int d = (int)(((long long)blockIdx.x * blockDim.x + threadIdx.x) >> 5);
    int lane = threadIdx.x & 31;
    if (d >= N) return;
    int beg = rowptr[d], endp = rowptr[d + 1];
    float ad = (lane < 8) ? adst[d * 8 + lane] : 0.f;
    float den = 0.f;
    float4 acc0 = {0, 0, 0, 0}, acc1 = {0, 0, 0, 0};
    int h0 = lane >> 3;
    for (int base = beg; base < endp; base += 32) {
        int nn = min(32, endp - base);
        int sreg = (base + lane < endp) ? esrc[base + lane] : 0;
        for (int j = 0; j < nn; j++) {
            int s = __shfl_sync(0xffffffffu, sreg, j);
            float wgt = 0.f;
            if (lane < 8) wgt = __expf(lrelu(asrc[s * 8 + lane] + ad));
            den += wgt;
            float a0 = __shfl_sync(0xffffffffu, wgt, h0);
            float a1 = __shfl_sync(0xffffffffu, wgt, h0 + 4);
            const float4* hp = reinterpret_cast<const float4*>(h1 + (size_t)s * 256);
            float4 v0 = hp[lane];
            float4 v1 = hp[lane + 32];
            acc0.x += v0.x * a0; acc0.y += v0.y * a0; acc0.z += v0.z * a0; acc0.w += v0.w * a0;
            acc1.x += v1.x * a1; acc1.y += v1.y * a1; acc1.z += v1.z * a1; acc1.w += v1.w * a1;
        }
    }
    float dn0 = __shfl_sync(0xffffffffu, den, h0);
    float dn1 = __shfl_sync(0xffffffffu, den, h0 + 4);
    float r0 = 1.f / dn0, r1 = 1.f / dn1;
    const float4* bp = reinterpret_cast<const float4*>(b1);
    float4 bb0 = bp[lane], bb1 = bp[lane + 32];
    float4 o0, o1;
    o0.x = eluf(acc0.x * r0 + bb0.x); o0.y = eluf(acc0.y * r0 + bb0.y);
    o0.z = eluf(acc0.z * r0 + bb0.z); o0.w = eluf(acc0.w * r0 + bb0.w);
    o1.x = eluf(acc1.x * r1 + bb1.x); o1.y = eluf(acc1.y * r1 + bb1.y);
    o1.z = eluf(acc1.z * r1 + bb1.z); o1.w = eluf(acc1.w * r1 + bb1.w);
    float4* op = reinterpret_cast<float4*>(out1 + (size_t)d * 256);
    op[lane] = o0;
    op[lane + 32] = o1;
}

// ----- GEMM2: h2 = x2[N,256] @ W2[256,16], fused alpha2 ----------------------
__global__ void k_gemm2(const float* __restrict__ x2, const float* __restrict__ W2,
                        const float* __restrict__ a_src2, const float* __restrict__ a_dst2,
                        float* __restrict__ h2, float* __restrict__ asrc2n,
                        float* __restrict__ adst2n, int N) {
    __shared__ float Wsh[256 * 16];
    int t = threadIdx.x;               // 256 threads -> 16 nodes x 16 cols
    for (int i = t; i < 4096; i += 256) Wsh[i] = W2[i];
    __syncthreads();
    int n = blockIdx.x * 16 + (t >> 4);
    int c = t & 15;
    if (n >= N) return;
    float acc = 0.f;
    const float4* xr = reinterpret_cast<const float4*>(x2 + (size_t)n * 256);
#pragma unroll 8
    for (int k4 = 0; k4 < 64; k4++) {
        float4 xv = xr[k4];
        acc += xv.x * Wsh[(k4 * 4 + 0) * 16 + c] + xv.y * Wsh[(k4 * 4 + 1) * 16 + c]
             + xv.z * Wsh[(k4 * 4 + 2) * 16 + c] + xv.w * Wsh[(k4 * 4 + 3) * 16 + c];
    }
    h2[(size_t)n * 16 + c] = acc;
    float r1 = acc * a_src2[c];
    float r2 = acc * a_dst2[c];
#pragma unroll
    for (int m = 8; m >= 1; m >>= 1) {
        r1 += __shfl_xor_sync(0xffffffffu, r1, m, 16);
        r2 += __shfl_xor_sync(0xffffffffu, r2, m, 16);
    }
    if (c == 0) { asrc2n[n] = r1; adst2n[n] = r2; }
}

// ----- GAT2 pull aggregation: 4 lanes per dst, fused softmax+bias+ELU --------
__global__ void k_agg2(const int* __restrict__ rowptr, const int* __restrict__ esrc,
                       const float* __restrict__ asrc, const float* __restrict__ adst,
                       const float* __restrict__ h2, const float* __restrict__ b2,
                       float* __restrict__ out2, int N) {
    long long gt = (long long)blockIdx.x * blockDim.x + threadIdx.x;
    int d = (int)(gt >> 2);
    int q = threadIdx.x & 3;
    if (d >= N) return;
    int beg = rowptr[d], endp = rowptr[d + 1];
    float ad = adst[d];
    float den = 0.f;
    float4 acc = {0, 0, 0, 0};
    for (int idx = beg; idx < endp; idx++) {
        int s = esrc[idx];
        float wgt = __expf(lrelu(asrc[s] + ad));
        den += wgt;
        float4 v = reinterpret_cast<const float4*>(h2 + (size_t)s * 16)[q];
        acc.x += v.x * wgt; acc.y += v.y * wgt; acc.z += v.z * wgt; acc.w += v.w * wgt;
    }
    float r = 1.f / den;
    float4 bb = reinterpret_cast<const float4*>(b2)[q];
    float4 o;
    o.x = eluf(acc.x * r + bb.x); o.y = eluf(acc.y * r + bb.y);
    o.z = eluf(acc.z * r + bb.z); o.w = eluf(acc.w * r + bb.w);
    reinterpret_cast<float4*>(out2 + (size_t)d * 16)[q] = o;
}

// ----- GCN transform: g = (x3 @ W3) * dinv[n], dinv from rowptr ---------------
__global__ void k_h3(const float* __restrict__ x3, const float* __restrict__ W3,
                     const int* __restrict__ rowptr, float* __restrict__ g, int N) {
    __shared__ float Wsh[256];
    if (threadIdx.x < 256) Wsh[threadIdx.x] = W3[threadIdx.x];
    __syncthreads();
    int n = blockIdx.x * blockDim.x + threadIdx.x;
    if (n >= N) return;
    float xr[16];
    const float4* xp = reinterpret_cast<const float4*>(x3 + (size_t)n * 16);
#pragma unroll
    for (int j = 0; j < 4; j++) {
        float4 v = xp[j];
        xr[4 * j + 0] = v.x; xr[4 * j + 1] = v.y; xr[4 * j + 2] = v.z; xr[4 * j + 3] = v.w;
    }
    float dv = rsqrtf((float)(rowptr[n + 1] - rowptr[n]));
    float* go = g + (size_t)n * 16;
#pragma unroll
    for (int c = 0; c < 16; c++) {
        float acc = 0.f;
#pragma unroll
        for (int k = 0; k < 16; k++) acc += xr[k] * Wsh[k * 16 + c];
        go[c] = acc * dv;
    }
}

// ----- GCN pull aggregation + finalize: 4 lanes per dst ----------------------
__global__ void k_agg3(const int* __restrict__ rowptr, const int* __restrict__ esrc,
                       const float* __restrict__ g, const float* __restrict__ b3,
                       float* __restrict__ out, int N) {
    long long gt = (long long)blockIdx.x * blockDim.x + threadIdx.x;
    int d = (int)(gt >> 2);
    int q = threadIdx.x & 3;
    if (d >= N) return;
    int beg = rowptr[d], endp = rowptr[d + 1];
    float4 acc = {0, 0, 0, 0};
    for (int idx = beg; idx < endp; idx++) {
        int s = esrc[idx];
        float4 v = reinterpret_cast<const float4*>(g + (size_t)s * 16)[q];
        acc.x += v.x; acc.y += v.y; acc.z += v.z; acc.w += v.w;
    }
    float dv = rsqrtf((float)(endp - beg));
    float4 bb = reinterpret_cast<const float4*>(b3)[q];
    float4 o;
    o.x = acc.x * dv + bb.x; o.y = acc.y * dv + bb.y;
    o.z = acc.z * dv + bb.z; o.w = acc.w * dv + bb.w;
    reinterpret_cast<float4*>(out + (size_t)d * 16)[q] = o;
}

// ---------------------------------------------------------------------------
extern "C" void kernel_launch(void* const* d_in, const int* in_sizes, int n_in,
                              void* d_out, int out_size) {
    const float* x      = (const float*)d_in[0];
    const int*   ei     = (const int*)d_in[1];
    const float* W1     = (const float*)d_in[2];
    const float* a_src1 = (const float*)d_in[3];
    const float* a_dst1 = (const float*)d_in[4];
    const float* b1     = (const float*)d_in[5];
    const float* W2     = (const float*)d_in[6];
    const float* a_src2 = (const float*)d_in[7];
    const float* a_dst2 = (const float*)d_in[8];
    const float* b2     = (const float*)d_in[9];
    const float* W3     = (const float*)d_in[10];
    const float* b3     = (const float*)d_in[11];
    float* out = (float*)d_out;

    const int N = in_sizes[0] / 128;
    const int E = in_sizes[1] / 2;
    const int ET = E + N;

    float *h1, *asrc1, *adst1, *out1, *h2, *asrc2, *adst2, *out2, *g;
    int *degi, *cursor, *rowptr, *esrc;
    void* p;
    cudaGetSymbolAddress(&p, g_h1);     h1     = (float*)p;
    cudaGetSymbolAddress(&p, g_asrc1);  asrc1  = (float*)p;
    cudaGetSymbolAddress(&p, g_adst1);  adst1  = (float*)p;
    cudaGetSymbolAddress(&p, g_out1);   out1   = (float*)p;
    cudaGetSymbolAddress(&p, g_h2);     h2     = (float*)p;
    cudaGetSymbolAddress(&p, g_asrc2);  asrc2  = (float*)p;
    cudaGetSymbolAddress(&p, g_adst2);  adst2  = (float*)p;
    cudaGetSymbolAddress(&p, g_out2);   out2   = (float*)p;
    cudaGetSymbolAddress(&p, g_g);      g      = (float*)p;
    cudaGetSymbolAddress(&p, g_degi);   degi   = (int*)p;
    cudaGetSymbolAddress(&p, g_cursor); cursor = (int*)p;
    cudaGetSymbolAddress(&p, g_rowptr); rowptr = (int*)p;
    cudaGetSymbolAddress(&p, g_esrc);   esrc   = (int*)p;

    cudaMemsetAsync(degi,   0, (size_t)N * sizeof(int), 0);
    cudaMemsetAsync(cursor, 0, (size_t)N * sizeof(int), 0);

    const int B = 256;

    // CSR build (shared by all three layers)
    k_deg<<<(ET + B - 1) / B, B>>>(ei, E, N, degi);
    k_scan<<<1, 1024>>>(degi, rowptr, N, ET);
    k_fill<<<(ET + B - 1) / B, B>>>(ei, E, N, rowptr, cursor, esrc);

    // Layer 1: GAT(128 -> 32 x 8 heads), tensor-core GEMM
    {
        dim3 grid((N + 63) / 64, 2);
        k_gemm1_tc<<<grid, 256>>>(x, W1, h1, N);
    }
    k_alpha1<<<(N * 8 + B - 1) / B, B>>>(h1, a_src1, a_dst1, asrc1, adst1, N);
    {
        long long tot = (long long)N * 32;   // warp per dst
        k_agg1<<<(unsigned)((tot + B - 1) / B), B>>>(rowptr, esrc, asrc1, adst1, h1, b1, out1, N);
    }

    // Layer 2: GAT(256 -> 16, 1 head)
    k_gemm2<<<(N + 15) / 16, B>>>(out1, W2, a_src2, a_dst2, h2, asrc2, adst2, N);
    {
        long long tot = (long long)N * 4;
        k_agg2<<<(unsigned)((tot + B - 1) / B), B>>>(rowptr, esrc, asrc2, adst2, h2, b2, out2, N);
    }

    // Layer 3: GCN(16 -> 16)
    k_h3<<<(N + B - 1) / B, B>>>(out2, W3, rowptr, g, N);
    {
        long long tot = (long long)N * 4;
        k_agg3<<<(unsigned)((tot + B - 1) / B), B>>>(rowptr, esrc, g, b3, out, N);
    }
}

// round 5
// speedup vs baseline: 1.9733x; 1.1633x over previous
#include <cuda_runtime.h>
#include <math.h>

#define NMAX 50000
#define EMAX 800000
#define ETMAX (EMAX + NMAX)

// ---------------- scratch (device globals) -----------------------------------
__device__ float g_h1[NMAX * 256];
__device__ float g_asrc1[NMAX * 8];
__device__ float g_adst1[NMAX * 8];
__device__ float g_out1[NMAX * 256];
__device__ float g_h2[NMAX * 16];
__device__ float g_asrc2[NMAX];
__device__ float g_adst2[NMAX];
__device__ float g_out2[NMAX * 16];
__device__ float g_g[NMAX * 16];
__device__ int   g_degi[NMAX];
__device__ int   g_cursor[NMAX];
__device__ int   g_rowptr[NMAX + 1];
__device__ int   g_esrc[ETMAX];
__device__ float2 g_xsp[NMAX * 128];     // x split into (hi,lo) tf32 pairs
__device__ float2 g_wsp[128 * 256];      // W1 split

__device__ __forceinline__ float lrelu(float x) { return x > 0.f ? x : 0.2f * x; }
__device__ __forceinline__ float eluf(float x) { return x > 0.f ? x : expm1f(x); }

// ---------------- CSR build ---------------------------------------------------
__global__ void k_deg(const int* __restrict__ ei, int E, int N, int* __restrict__ degi) {
    int e = blockIdx.x * blockDim.x + threadIdx.x;
    int ET = E + N;
    if (e >= ET) return;
    int d = (e < E) ? ei[E + e] : e - E;
    atomicAdd(&degi[d], 1);
}

__global__ void k_scan(const int* __restrict__ degi, int* __restrict__ rowptr,
                       int N, int ET) {
    __shared__ int sh[1024];
    int t = threadIdx.x;
    int chunk = (N + 1023) / 1024;
    int start = t * chunk;
    int end = min(start + chunk, N);
    int sum = 0;
    for (int i = start; i < end; i++) sum += degi[i];
    sh[t] = sum;
    __syncthreads();
    for (int off = 1; off < 1024; off <<= 1) {
        int v = (t >= off) ? sh[t - off] : 0;
        __syncthreads();
        sh[t] += v;
        __syncthreads();
    }
    int run = (t == 0) ? 0 : sh[t - 1];
    for (int i = start; i < end; i++) { rowptr[i] = run; run += degi[i]; }
    if (t == 1023) rowptr[N] = ET;
}

__global__ void k_fill(const int* __restrict__ ei, int E, int N,
                       const int* __restrict__ rowptr, int* __restrict__ cursor,
                       int* __restrict__ esrc) {
    int e = blockIdx.x * blockDim.x + threadIdx.x;
    int ET = E + N;
    if (e >= ET) return;
    int s, d;
    if (e < E) { s = ei[e]; d = ei[E + e]; } else { s = d = e - E; }
    int pos = rowptr[d] + atomicAdd(&cursor[d], 1);
    esrc[pos] = s;
}

// ---------------- tf32 helpers ------------------------------------------------
__device__ __forceinline__ float2 tf32split2(float x) {
    unsigned u;
    asm("cvt.rna.tf32.f32 %0, %1;" : "=r"(u) : "f"(x));
    float hi = __uint_as_float(u);
    float r = x - hi;
    unsigned ul;
    asm("cvt.rna.tf32.f32 %0, %1;" : "=r"(ul) : "f"(r));
    return make_float2(hi, __uint_as_float(ul));
}

__device__ __forceinline__ void mma_tf32(float* d, const unsigned* a, const unsigned* b) {
    asm volatile("mma.sync.aligned.m16n8k8.row.col.f32.tf32.tf32.f32 "
                 "{%0,%1,%2,%3}, {%4,%5,%6,%7}, {%8,%9}, {%0,%1,%2,%3};"
                 : "+f"(d[0]), "+f"(d[1]), "+f"(d[2]), "+f"(d[3])
                 : "r"(a[0]), "r"(a[1]), "r"(a[2]), "r"(a[3]),
                   "r"(b[0]), "r"(b[1]));
}

__device__ __forceinline__ void cpasync16(void* dst, const void* src) {
    unsigned d = (unsigned)__cvta_generic_to_shared(dst);
    asm volatile("cp.async.cg.shared.global [%0], [%1], 16;" :: "r"(d), "l"(src));
}

// ---------------- split pass: f32 -> interleaved (hi,lo) ----------------------
__global__ void k_split(const float* __restrict__ src, float2* __restrict__ dst,
                        int total4) {
    int i = blockIdx.x * blockDim.x + threadIdx.x;
    if (i >= total4) return;
    float4 v = reinterpret_cast<const float4*>(src)[i];
    float2 o0 = tf32split2(v.x), o1 = tf32split2(v.y);
    float2 o2 = tf32split2(v.z), o3 = tf32split2(v.w);
    float4* d = reinterpret_cast<float4*>(dst + (size_t)i * 4);
    d[0] = make_float4(o0.x, o0.y, o1.x, o1.y);
    d[1] = make_float4(o2.x, o2.y, o3.x, o3.y);
}

// ---------------- GEMM1 (tensor core, pre-split tf32, fused alpha) ------------
// block tile 128m x 128n, 8 warps (2x4), warp tile 64x32, k-chunk 16, 2 stages
#define AS_STRIDE 20
#define AS_STAGE  (128 * AS_STRIDE)
#define BS_STRIDE 132
#define BS_STAGE  (16 * BS_STRIDE)
#define SMEM_F2   (2 * AS_STAGE + 2 * BS_STAGE)

__global__ __launch_bounds__(256) void k_gemm1_tc2(
        const float2* __restrict__ xsp, const float2* __restrict__ wsp,
        const float* __restrict__ a_src, const float* __restrict__ a_dst,
        float* __restrict__ h1, float* __restrict__ asrcn, float* __restrict__ adstn,
        int N) {
    extern __shared__ float2 smem[];
    const int t = threadIdx.x;
    const int warp = t >> 5, lane = t & 31;
    const int wm = warp >> 2, wn = warp & 3;
    const int lm = lane >> 2, lk = lane & 3;
    const int r0 = blockIdx.x * 128;
    const int n0 = blockIdx.y * 128;

    float acc[4][4][4];
#pragma unroll
    for (int i = 0; i < 4; i++)
#pragma unroll
        for (int j = 0; j < 4; j++)
#pragma unroll
            for (int v = 0; v < 4; v++) acc[i][j][v] = 0.f;

    // async tile loaders: chunk c covers k in [c*16, c*16+16)
    auto issue = [&](int c, int buf) {
        int k0 = c * 16;
        float2* As = smem + buf * AS_STAGE;
        float2* Bs = smem + 2 * AS_STAGE + buf * BS_STAGE;
#pragma unroll
        for (int i = 0; i < 4; i++) {            // A: 1024 x 16B
            int op = t + i * 256;
            int row = op >> 3, seg = op & 7;
            int gr = r0 + row; if (gr > N - 1) gr = N - 1;
            cpasync16(As + row * AS_STRIDE + seg * 2,
                      xsp + (size_t)gr * 128 + k0 + seg * 2);
        }
#pragma unroll
        for (int i = 0; i < 4; i++) {            // B: 1024 x 16B
            int op = t + i * 256;
            int row = op >> 6, seg = op & 63;
            cpasync16(Bs + row * BS_STRIDE + seg * 2,
                      wsp + (size_t)(k0 + row) * 256 + n0 + seg * 2);
        }
        asm volatile("cp.async.commit_group;");
    };

    issue(0, 0);
    for (int c = 0; c < 8; c++) {
        int buf = c & 1;
        if (c < 7) {
            issue(c + 1, buf ^ 1);
            asm volatile("cp.async.wait_group 1;");
        } else {
            asm volatile("cp.async.wait_group 0;");
        }
        __syncthreads();
        const float2* As = smem + buf * AS_STAGE;
        const float2* Bs = smem + 2 * AS_STAGE + buf * BS_STAGE;
#pragma unroll
        for (int ks = 0; ks < 16; ks += 8) {
            unsigned Ah[4][4], Al[4][4];
#pragma unroll
            for (int mt = 0; mt < 4; mt++) {
                int mrow = wm * 64 + mt * 16 + lm;
                int c1 = ks + lk, c2 = c1 + 4;
                float2 p0 = As[mrow * AS_STRIDE + c1];
                float2 p1 = As[(mrow + 8) * AS_STRIDE + c1];
                float2 p2 = As[mrow * AS_STRIDE + c2];
                float2 p3 = As[(mrow + 8) * AS_STRIDE + c2];
                Ah[mt][0] = __float_as_uint(p0.x); Al[mt][0] = __float_as_uint(p0.y);
                Ah[mt][1] = __float_as_uint(p1.x); Al[mt][1] = __float_as_uint(p1.y);
                Ah[mt][2] = __float_as_uint(p2.x); Al[mt][2] = __float_as_uint(p2.y);
                Ah[mt][3] = __float_as_uint(p3.x); Al[mt][3] = __float_as_uint(p3.y);
            }
            unsigned Bh[4][2], Bl[4][2];
#pragma unroll
            for (int nt = 0; nt < 4; nt++) {
                int n = wn * 32 + nt * 8 + lm;
                float2 q0 = Bs[(ks + lk) * BS_STRIDE + n];
                float2 q1 = Bs[(ks + lk + 4) * BS_STRIDE + n];
                Bh[nt][0] = __float_as_uint(q0.x); Bl[nt][0] = __float_as_uint(q0.y);
                Bh[nt][1] = __float_as_uint(q1.x); Bl[nt][1] = __float_as_uint(q1.y);
            }
#pragma unroll
            for (int mt = 0; mt < 4; mt++)
#pragma unroll
                for (int nt = 0; nt < 4; nt++) {
                    mma_tf32(acc[mt][nt], Ah[mt], Bh[nt]);
                    mma_tf32(acc[mt][nt], Ah[mt], Bl[nt]);
                    mma_tf32(acc[mt][nt], Al[mt], Bh[nt]);
                }
        }
        __syncthreads();
    }

    // ---- epilogue: store h1 + fused alpha projections ----
    const int h = blockIdx.y * 4 + wn;         // this warp's head
    float2 asv[4], adv[4];
#pragma unroll
    for (int nt = 0; nt < 4; nt++) {
        asv[nt] = *reinterpret_cast<const float2*>(a_src + h * 32 + nt * 8 + lk * 2);
        adv[nt] = *reinterpret_cast<const float2*>(a_dst + h * 32 + nt * 8 + lk * 2);
    }
#pragma unroll
    for (int mt = 0; mt < 4; mt++) {
        int row1 = r0 + wm * 64 + mt * 16 + lm;
        int row2 = row1 + 8;
        float s1 = 0.f, d1 = 0.f, s2 = 0.f, d2 = 0.f;
#pragma unroll
        for (int nt = 0; nt < 4; nt++) {
            int col = n0 + wn * 32 + nt * 8 + lk * 2;
            s1 += acc[mt][nt][0] * asv[nt].x + acc[mt][nt][1] * asv[nt].y;
            d1 += acc[mt][nt][0] * adv[nt].x + acc[mt][nt][1] * adv[nt].y;
            s2 += acc[mt][nt][2] * asv[nt].x + acc[mt][nt][3] * asv[nt].y;
            d2 += acc[mt][nt][2] * adv[nt].x + acc[mt][nt][3] * adv[nt].y;
            if (row1 < N)
                *reinterpret_cast<float2*>(h1 + (size_t)row1 * 256 + col) =
                    make_float2(acc[mt][nt][0], acc[mt][nt][1]);
            if (row2 < N)
                *reinterpret_cast<float2*>(h1 + (size_t)row2 * 256 + col) =
                    make_float2(acc[mt][nt][2], acc[mt][nt][3]);
        }
        s1 += __shfl_xor_sync(0xffffffffu, s1, 1); s1 += __shfl_xor_sync(0xffffffffu, s1, 2);
        d1 += __shfl_xor_sync(0xffffffffu, d1, 1); d1 += __shfl_xor_sync(0xffffffffu, d1, 2);
        s2 += __shfl_xor_sync(0xffffffffu, s2, 1); s2 += __shfl_xor_sync(0xffffffffu, s2, 2);
        d2 += __shfl_xor_sync(0xffffffffu, d2, 1); d2 += __shfl_xor_sync(0xffffffffu, d2, 2);
        if (lk == 0) {
            if (row1 < N) { asrcn[row1 * 8 + h] = s1; adstn[row1 * 8 + h] = d1; }
            if (row2 < N) { asrcn[row2 * 8 + h] = s2; adstn[row2 * 8 + h] = d2; }
        }
    }
}

// ----- GAT1 pull aggregation: warp per dst, fused softmax+bias+ELU -----------
__global__ void k_agg1(const int* __restrict__ rowptr, const int* __restrict__ esrc,
                       const float* __restrict__ asrc, const float* __restrict__ adst,
                       const float* __restrict__ h1, const float* __restrict__ b1,
                       float* __restrict__ out1, int N) {
    int d = (int)(((long long)blockIdx.x * blockDim.x + threadIdx.x) >> 5);
    int lane = threadIdx.x & 31;
    if (d >= N) return;
    int beg = rowptr[d], endp = rowptr[d + 1];
    float ad = (lane < 8) ? adst[d * 8 + lane] : 0.f;
    float den = 0.f;
    float4 acc0 = {0, 0, 0, 0}, acc1 = {0, 0, 0, 0};
    int h0 = lane >> 3;
    for (int base = beg; base < endp; base += 32) {
        int nn = min(32, endp - base);
        int sreg = (base + lane < endp) ? esrc[base + lane] : 0;
        for (int j = 0; j < nn; j++) {
            int s = __shfl_sync(0xffffffffu, sreg, j);
            float wgt = 0.f;
            if (lane < 8) wgt = __expf(lrelu(asrc[s * 8 + lane] + ad));
            den += wgt;
            float a0 = __shfl_sync(0xffffffffu, wgt, h0);
            float a1 = __shfl_sync(0xffffffffu, wgt, h0 + 4);
            const float4* hp = reinterpret_cast<const float4*>(h1 + (size_t)s * 256);
            float4 v0 = hp[lane];
            float4 v1 = hp[lane + 32];
            acc0.x += v0.x * a0; acc0.y += v0.y * a0; acc0.z += v0.z * a0; acc0.w += v0.w * a0;
            acc1.x += v1.x * a1; acc1.y += v1.y * a1; acc1.z += v1.z * a1; acc1.w += v1.w * a1;
        }
    }
    float dn0 = __shfl_sync(0xffffffffu, den, h0);
    float dn1 = __shfl_sync(0xffffffffu, den, h0 + 4);
    float r0 = 1.f / dn0, r1 = 1.f / dn1;
    const float4* bp = reinterpret_cast<const float4*>(b1);
    float4 bb0 = bp[lane], bb1 = bp[lane + 32];
    float4 o0, o1;
    o0.x = eluf(acc0.x * r0 + bb0.x); o0.y = eluf(acc0.y * r0 + bb0.y);
    o0.z = eluf(acc0.z * r0 + bb0.z); o0.w = eluf(acc0.w * r0 + bb0.w);
    o1.x = eluf(acc1.x * r1 + bb1.x); o1.y = eluf(acc1.y * r1 + bb1.y);
    o1.z = eluf(acc1.z * r1 + bb1.z); o1.w = eluf(acc1.w * r1 + bb1.w);
    float4* op = reinterpret_cast<float4*>(out1 + (size_t)d * 256);
    op[lane] = o0;
    op[lane + 32] = o1;
}

// ----- GEMM2: h2 = x2[N,256] @ W2[256,16], fused alpha2 ----------------------
__global__ void k_gemm2(const float* __restrict__ x2, const float* __restrict__ W2,
                        const float* __restrict__ a_src2, const float* __restrict__ a_dst2,
                        float* __restrict__ h2, float* __restrict__ asrc2n,
                        float* __restrict__ adst2n, int N) {
    __shared__ float Wsh[256 * 16];
    int t = threadIdx.x;
    for (int i = t; i < 4096; i += 256) Wsh[i] = W2[i];
    __syncthreads();
    int n = blockIdx.x * 16 + (t >> 4);
    int c = t & 15;
    if (n >= N) return;
    float acc = 0.f;
    const float4* xr = reinterpret_cast<const float4*>(x2 + (size_t)n * 256);
#pragma unroll 8
    for (int k4 = 0; k4 < 64; k4++) {
        float4 xv = xr[k4];
        acc += xv.x * Wsh[(k4 * 4 + 0) * 16 + c] + xv.y * Wsh[(k4 * 4 + 1) * 16 + c]
             + xv.z * Wsh[(k4 * 4 + 2) * 16 + c] + xv.w * Wsh[(k4 * 4 + 3) * 16 + c];
    }
    h2[(size_t)n * 16 + c] = acc;
    float r1 = acc * a_src2[c];
    float r2 = acc * a_dst2[c];
#pragma unroll
    for (int m = 8; m >= 1; m >>= 1) {
        r1 += __shfl_xor_sync(0xffffffffu, r1, m, 16);
        r2 += __shfl_xor_sync(0xffffffffu, r2, m, 16);
    }
    if (c == 0) { asrc2n[n] = r1; adst2n[n] = r2; }
}

// ----- GAT2 pull aggregation: 4 lanes per dst ---------------------------------
__global__ void k_agg2(const int* __restrict__ rowptr, const int* __restrict__ esrc,
                       const float* __restrict__ asrc, const float* __restrict__ adst,
                       const float* __restrict__ h2, const float* __restrict__ b2,
                       float* __restrict__ out2, int N) {
    long long gt = (long long)blockIdx.x * blockDim.x + threadIdx.x;
    int d = (int)(gt >> 2);
    int q = threadIdx.x & 3;
    if (d >= N) return;
    int beg = rowptr[d], endp = rowptr[d + 1];
    float ad = adst[d];
    float den = 0.f;
    float4 acc = {0, 0, 0, 0};
    for (int idx = beg; idx < endp; idx++) {
        int s = esrc[idx];
        float wgt = __expf(lrelu(asrc[s] + ad));
        den += wgt;
        float4 v = reinterpret_cast<const float4*>(h2 + (size_t)s * 16)[q];
        acc.x += v.x * wgt; acc.y += v.y * wgt; acc.z += v.z * wgt; acc.w += v.w * wgt;
    }
    float r = 1.f / den;
    float4 bb = reinterpret_cast<const float4*>(b2)[q];
    float4 o;
    o.x = eluf(acc.x * r + bb.x); o.y = eluf(acc.y * r + bb.y);
    o.z = eluf(acc.z * r + bb.z); o.w = eluf(acc.w * r + bb.w);
    reinterpret_cast<float4*>(out2 + (size_t)d * 16)[q] = o;
}

// ----- GCN transform ----------------------------------------------------------
__global__ void k_h3(const float* __restrict__ x3, const float* __restrict__ W3,
                     const int* __restrict__ rowptr, float* __restrict__ g, int N) {
    __shared__ float Wsh[256];
    if (threadIdx.x < 256) Wsh[threadIdx.x] = W3[threadIdx.x];
    __syncthreads();
    int n = blockIdx.x * blockDim.x + threadIdx.x;
    if (n >= N) return;
    float xr[16];
    const float4* xp = reinterpret_cast<const float4*>(x3 + (size_t)n * 16);
#pragma unroll
    for (int j = 0; j < 4; j++) {
        float4 v = xp[j];
        xr[4 * j + 0] = v.x; xr[4 * j + 1] = v.y; xr[4 * j + 2] = v.z; xr[4 * j + 3] = v.w;
    }
    float dv = rsqrtf((float)(rowptr[n + 1] - rowptr[n]));
    float* go = g + (size_t)n * 16;
#pragma unroll
    for (int c = 0; c < 16; c++) {
        float acc = 0.f;
#pragma unroll
        for (int k = 0; k < 16; k++) acc += xr[k] * Wsh[k * 16 + c];
        go[c] = acc * dv;
    }
}

// ----- GCN pull aggregation + finalize ----------------------------------------
__global__ void k_agg3(const int* __restrict__ rowptr, const int* __restrict__ esrc,
                       const float* __restrict__ g, const float* __restrict__ b3,
                       float* __restrict__ out, int N) {
    long long gt = (long long)blockIdx.x * blockDim.x + threadIdx.x;
    int d = (int)(gt >> 2);
    int q = threadIdx.x & 3;
    if (d >= N) return;
    int beg = rowptr[d], endp = rowptr[d + 1];
    float4 acc = {0, 0, 0, 0};
    for (int idx = beg; idx < endp; idx++) {
        int s = esrc[idx];
        float4 v = reinterpret_cast<const float4*>(g + (size_t)s * 16)[q];
        acc.x += v.x; acc.y += v.y; acc.z += v.z; acc.w += v.w;
    }
    float dv = rsqrtf((float)(endp - beg));
    float4 bb = reinterpret_cast<const float4*>(b3)[q];
    float4 o;
    o.x = acc.x * dv + bb.x; o.y = acc.y * dv + bb.y;
    o.z = acc.z * dv + bb.z; o.w = acc.w * dv + bb.w;
    reinterpret_cast<float4*>(out + (size_t)d * 16)[q] = o;
}

// ---------------------------------------------------------------------------
extern "C" void kernel_launch(void* const* d_in, const int* in_sizes, int n_in,
                              void* d_out, int out_size) {
    const float* x      = (const float*)d_in[0];
    const int*   ei     = (const int*)d_in[1];
    const float* W1     = (const float*)d_in[2];
    const float* a_src1 = (const float*)d_in[3];
    const float* a_dst1 = (const float*)d_in[4];
    const float* b1     = (const float*)d_in[5];
    const float* W2     = (const float*)d_in[6];
    const float* a_src2 = (const float*)d_in[7];
    const float* a_dst2 = (const float*)d_in[8];
    const float* b2     = (const float*)d_in[9];
    const float* W3     = (const float*)d_in[10];
    const float* b3     = (const float*)d_in[11];
    float* out = (float*)d_out;

    const int N = in_sizes[0] / 128;
    const int E = in_sizes[1] / 2;
    const int ET = E + N;

    float *h1, *asrc1, *adst1, *out1, *h2, *asrc2, *adst2, *out2, *g;
    int *degi, *cursor, *rowptr, *esrc;
    float2 *xsp, *wsp;
    void* p;
    cudaGetSymbolAddress(&p, g_h1);     h1     = (float*)p;
    cudaGetSymbolAddress(&p, g_asrc1);  asrc1  = (float*)p;
    cudaGetSymbolAddress(&p, g_adst1);  adst1  = (float*)p;
    cudaGetSymbolAddress(&p, g_out1);   out1   = (float*)p;
    cudaGetSymbolAddress(&p, g_h2);     h2     = (float*)p;
    cudaGetSymbolAddress(&p, g_asrc2);  asrc2  = (float*)p;
    cudaGetSymbolAddress(&p, g_adst2);  adst2  = (float*)p;
    cudaGetSymbolAddress(&p, g_out2);   out2   = (float*)p;
    cudaGetSymbolAddress(&p, g_g);      g      = (float*)p;
    cudaGetSymbolAddress(&p, g_degi);   degi   = (int*)p;
    cudaGetSymbolAddress(&p, g_cursor); cursor = (int*)p;
    cudaGetSymbolAddress(&p, g_rowptr); rowptr = (int*)p;
    cudaGetSymbolAddress(&p, g_esrc);   esrc   = (int*)p;
    cudaGetSymbolAddress(&p, g_xsp);    xsp    = (float2*)p;
    cudaGetSymbolAddress(&p, g_wsp);    wsp    = (float2*)p;

    cudaMemsetAsync(degi,   0, (size_t)N * sizeof(int), 0);
    cudaMemsetAsync(cursor, 0, (size_t)N * sizeof(int), 0);

    const int B = 256;

    // CSR build (shared by all three layers)
    k_deg<<<(ET + B - 1) / B, B>>>(ei, E, N, degi);
    k_scan<<<1, 1024>>>(degi, rowptr, N, ET);
    k_fill<<<(ET + B - 1) / B, B>>>(ei, E, N, rowptr, cursor, esrc);

    // pre-split x and W1 into tf32 (hi,lo) pairs
    k_split<<<(N * 32 + B - 1) / B, B>>>(x, xsp, N * 32);
    k_split<<<(8192 + B - 1) / B, B>>>(W1, wsp, 8192);

    // Layer 1: GAT(128 -> 32 x 8 heads): tensor-core GEMM with fused alpha
    {
        static int smem_set = 0;
        if (!smem_set) {
            cudaFuncSetAttribute(k_gemm1_tc2,
                                 cudaFuncAttributeMaxDynamicSharedMemorySize,
                                 SMEM_F2 * (int)sizeof(float2));
            smem_set = 1;
        }
        dim3 grid((N + 127) / 128, 2);
        k_gemm1_tc2<<<grid, 256, SMEM_F2 * sizeof(float2)>>>(
            xsp, wsp, a_src1, a_dst1, h1, asrc1, adst1, N);
    }
    {
        long long tot = (long long)N * 32;   // warp per dst
        k_agg1<<<(unsigned)((tot + B - 1) / B), B>>>(rowptr, esrc, asrc1, adst1, h1, b1, out1, N);
    }

    // Layer 2: GAT(256 -> 16, 1 head)
    k_gemm2<<<(N + 15) / 16, B>>>(out1, W2, a_src2, a_dst2, h2, asrc2, adst2, N);
    {
        long long tot = (long long)N * 4;
        k_agg2<<<(unsigned)((tot + B - 1) / B), B>>>(rowptr, esrc, asrc2, adst2, h2, b2, out2, N);
    }

    // Layer 3: GCN(16 -> 16)
    k_h3<<<(N + B - 1) / B, B>>>(out2, W3, rowptr, g, N);
    {
        long long tot = (long long)N * 4;
        k_agg3<<<(unsigned)((tot + B - 1) / B), B>>>(rowptr, esrc, g, b3, out, N);
    }
}

// round 6
// speedup vs baseline: 1.9944x; 1.0107x over previous
#include <cuda_runtime.h>
#include <math.h>

#define NMAX 50000
#define EMAX 800000
#define ETMAX (EMAX + NMAX)

// ---------------- scratch (device globals) -----------------------------------
__device__ float g_h1[NMAX * 256];
__device__ float g_asrc1[NMAX * 8];
__device__ float g_adst1[NMAX * 8];
__device__ float g_out1[NMAX * 256];
__device__ float g_h2[NMAX * 16];
__device__ float g_asrc2[NMAX];
__device__ float g_adst2[NMAX];
__device__ float g_out2[NMAX * 16];
__device__ float g_g[NMAX * 16];
__device__ int   g_degi[NMAX];
__device__ int   g_cursor[NMAX];
__device__ int   g_rowptr[NMAX + 1];
__device__ int   g_esrc[ETMAX];
__device__ float2 g_xsp[NMAX * 128];     // x split into (hi,lo) tf32 pairs
__device__ float2 g_wsp[128 * 256];      // W1 split

__device__ __forceinline__ float lrelu(float x) { return x > 0.f ? x : 0.2f * x; }
__device__ __forceinline__ float eluf(float x) { return x > 0.f ? x : expm1f(x); }

// ---------------- CSR build ---------------------------------------------------
__global__ void k_deg(const int* __restrict__ ei, int E, int N, int* __restrict__ degi) {
    int e = blockIdx.x * blockDim.x + threadIdx.x;
    int ET = E + N;
    if (e >= ET) return;
    int d = (e < E) ? ei[E + e] : e - E;
    atomicAdd(&degi[d], 1);
}

__global__ void k_scan(const int* __restrict__ degi, int* __restrict__ rowptr,
                       int N, int ET) {
    __shared__ int sh[1024];
    int t = threadIdx.x;
    int chunk = (N + 1023) / 1024;
    int start = t * chunk;
    int end = min(start + chunk, N);
    int sum = 0;
    for (int i = start; i < end; i++) sum += degi[i];
    sh[t] = sum;
    __syncthreads();
    for (int off = 1; off < 1024; off <<= 1) {
        int v = (t >= off) ? sh[t - off] : 0;
        __syncthreads();
        sh[t] += v;
        __syncthreads();
    }
    int run = (t == 0) ? 0 : sh[t - 1];
    for (int i = start; i < end; i++) { rowptr[i] = run; run += degi[i]; }
    if (t == 1023) rowptr[N] = ET;
}

__global__ void k_fill(const int* __restrict__ ei, int E, int N,
                       const int* __restrict__ rowptr, int* __restrict__ cursor,
                       int* __restrict__ esrc) {
    int e = blockIdx.x * blockDim.x + threadIdx.x;
    int ET = E + N;
    if (e >= ET) return;
    int s, d;
    if (e < E) { s = ei[e]; d = ei[E + e]; } else { s = d = e - E; }
    int pos = rowptr[d] + atomicAdd(&cursor[d], 1);
    esrc[pos] = s;
}

// ---------------- tf32 helpers ------------------------------------------------
__device__ __forceinline__ float2 tf32split2(float x) {
    unsigned u;
    asm("cvt.rna.tf32.f32 %0, %1;" : "=r"(u) : "f"(x));
    float hi = __uint_as_float(u);
    float r = x - hi;
    unsigned ul;
    asm("cvt.rna.tf32.f32 %0, %1;" : "=r"(ul) : "f"(r));
    return make_float2(hi, __uint_as_float(ul));
}

__device__ __forceinline__ void mma_tf32(float* d, const unsigned* a, const unsigned* b) {
    asm volatile("mma.sync.aligned.m16n8k8.row.col.f32.tf32.tf32.f32 "
                 "{%0,%1,%2,%3}, {%4,%5,%6,%7}, {%8,%9}, {%0,%1,%2,%3};"
                 : "+f"(d[0]), "+f"(d[1]), "+f"(d[2]), "+f"(d[3])
                 : "r"(a[0]), "r"(a[1]), "r"(a[2]), "r"(a[3]),
                   "r"(b[0]), "r"(b[1]));
}

__device__ __forceinline__ void cpasync16(void* dst, const void* src) {
    unsigned d = (unsigned)__cvta_generic_to_shared(dst);
    asm volatile("cp.async.cg.shared.global [%0], [%1], 16;" :: "r"(d), "l"(src));
}

// ---------------- split pass: f32 -> interleaved (hi,lo) ----------------------
__global__ void k_split(const float* __restrict__ src, float2* __restrict__ dst,
                        int total4) {
    int i = blockIdx.x * blockDim.x + threadIdx.x;
    if (i >= total4) return;
    float4 v = reinterpret_cast<const float4*>(src)[i];
    float2 o0 = tf32split2(v.x), o1 = tf32split2(v.y);
    float2 o2 = tf32split2(v.z), o3 = tf32split2(v.w);
    float4* d = reinterpret_cast<float4*>(dst + (size_t)i * 4);
    d[0] = make_float4(o0.x, o0.y, o1.x, o1.y);
    d[1] = make_float4(o2.x, o2.y, o3.x, o3.y);
}

// ---------------- GEMM1 (tensor core, pre-split tf32, fused alpha) ------------
#define AS_STRIDE 20
#define AS_STAGE  (128 * AS_STRIDE)
#define BS_STRIDE 132
#define BS_STAGE  (16 * BS_STRIDE)
#define SMEM_F2   (2 * AS_STAGE + 2 * BS_STAGE)

__global__ __launch_bounds__(256) void k_gemm1_tc2(
        const float2* __restrict__ xsp, const float2* __restrict__ wsp,
        const float* __restrict__ a_src, const float* __restrict__ a_dst,
        float* __restrict__ h1, float* __restrict__ asrcn, float* __restrict__ adstn,
        int N) {
    extern __shared__ float2 smem[];
    const int t = threadIdx.x;
    const int warp = t >> 5, lane = t & 31;
    const int wm = warp >> 2, wn = warp & 3;
    const int lm = lane >> 2, lk = lane & 3;
    const int r0 = blockIdx.x * 128;
    const int n0 = blockIdx.y * 128;

    float acc[4][4][4];
#pragma unroll
    for (int i = 0; i < 4; i++)
#pragma unroll
        for (int j = 0; j < 4; j++)
#pragma unroll
            for (int v = 0; v < 4; v++) acc[i][j][v] = 0.f;

    auto issue = [&](int c, int buf) {
        int k0 = c * 16;
        float2* As = smem + buf * AS_STAGE;
        float2* Bs = smem + 2 * AS_STAGE + buf * BS_STAGE;
#pragma unroll
        for (int i = 0; i < 4; i++) {
            int op = t + i * 256;
            int row = op >> 3, seg = op & 7;
            int gr = r0 + row; if (gr > N - 1) gr = N - 1;
            cpasync16(As + row * AS_STRIDE + seg * 2,
                      xsp + (size_t)gr * 128 + k0 + seg * 2);
        }
#pragma unroll
        for (int i = 0; i < 4; i++) {
            int op = t + i * 256;
            int row = op >> 6, seg = op & 63;
            cpasync16(Bs + row * BS_STRIDE + seg * 2,
                      wsp + (size_t)(k0 + row) * 256 + n0 + seg * 2);
        }
        asm volatile("cp.async.commit_group;");
    };

    issue(0, 0);
    for (int c = 0; c < 8; c++) {
        int buf = c & 1;
        if (c < 7) {
            issue(c + 1, buf ^ 1);
            asm volatile("cp.async.wait_group 1;");
        } else {
            asm volatile("cp.async.wait_group 0;");
        }
        __syncthreads();
        const float2* As = smem + buf * AS_STAGE;
        const float2* Bs = smem + 2 * AS_STAGE + buf * BS_STAGE;
#pragma unroll
        for (int ks = 0; ks < 16; ks += 8) {
            unsigned Ah[4][4], Al[4][4];
#pragma unroll
            for (int mt = 0; mt < 4; mt++) {
                int mrow = wm * 64 + mt * 16 + lm;
                int c1 = ks + lk, c2 = c1 + 4;
                float2 p0 = As[mrow * AS_STRIDE + c1];
                float2 p1 = As[(mrow + 8) * AS_STRIDE + c1];
                float2 p2 = As[mrow * AS_STRIDE + c2];
                float2 p3 = As[(mrow + 8) * AS_STRIDE + c2];
                Ah[mt][0] = __float_as_uint(p0.x); Al[mt][0] = __float_as_uint(p0.y);
                Ah[mt][1] = __float_as_uint(p1.x); Al[mt][1] = __float_as_uint(p1.y);
                Ah[mt][2] = __float_as_uint(p2.x); Al[mt][2] = __float_as_uint(p2.y);
                Ah[mt][3] = __float_as_uint(p3.x); Al[mt][3] = __float_as_uint(p3.y);
            }
            unsigned Bh[4][2], Bl[4][2];
#pragma unroll
            for (int nt = 0; nt < 4; nt++) {
                int n = wn * 32 + nt * 8 + lm;
                float2 q0 = Bs[(ks + lk) * BS_STRIDE + n];
                float2 q1 = Bs[(ks + lk + 4) * BS_STRIDE + n];
                Bh[nt][0] = __float_as_uint(q0.x); Bl[nt][0] = __float_as_uint(q0.y);
                Bh[nt][1] = __float_as_uint(q1.x); Bl[nt][1] = __float_as_uint(q1.y);
            }
#pragma unroll
            for (int mt = 0; mt < 4; mt++)
#pragma unroll
                for (int nt = 0; nt < 4; nt++) {
                    mma_tf32(acc[mt][nt], Ah[mt], Bh[nt]);
                    mma_tf32(acc[mt][nt], Ah[mt], Bl[nt]);
                    mma_tf32(acc[mt][nt], Al[mt], Bh[nt]);
                }
        }
        __syncthreads();
    }

    const int h = blockIdx.y * 4 + wn;
    float2 asv[4], adv[4];
#pragma unroll
    for (int nt = 0; nt < 4; nt++) {
        asv[nt] = *reinterpret_cast<const float2*>(a_src + h * 32 + nt * 8 + lk * 2);
        adv[nt] = *reinterpret_cast<const float2*>(a_dst + h * 32 + nt * 8 + lk * 2);
    }
#pragma unroll
    for (int mt = 0; mt < 4; mt++) {
        int row1 = r0 + wm * 64 + mt * 16 + lm;
        int row2 = row1 + 8;
        float s1 = 0.f, d1 = 0.f, s2 = 0.f, d2 = 0.f;
#pragma unroll
        for (int nt = 0; nt < 4; nt++) {
            int col = n0 + wn * 32 + nt * 8 + lk * 2;
            s1 += acc[mt][nt][0] * asv[nt].x + acc[mt][nt][1] * asv[nt].y;
            d1 += acc[mt][nt][0] * adv[nt].x + acc[mt][nt][1] * adv[nt].y;
            s2 += acc[mt][nt][2] * asv[nt].x + acc[mt][nt][3] * asv[nt].y;
            d2 += acc[mt][nt][2] * adv[nt].x + acc[mt][nt][3] * adv[nt].y;
            if (row1 < N)
                *reinterpret_cast<float2*>(h1 + (size_t)row1 * 256 + col) =
                    make_float2(acc[mt][nt][0], acc[mt][nt][1]);
            if (row2 < N)
                *reinterpret_cast<float2*>(h1 + (size_t)row2 * 256 + col) =
                    make_float2(acc[mt][nt][2], acc[mt][nt][3]);
        }
        s1 += __shfl_xor_sync(0xffffffffu, s1, 1); s1 += __shfl_xor_sync(0xffffffffu, s1, 2);
        d1 += __shfl_xor_sync(0xffffffffu, d1, 1); d1 += __shfl_xor_sync(0xffffffffu, d1, 2);
        s2 += __shfl_xor_sync(0xffffffffu, s2, 1); s2 += __shfl_xor_sync(0xffffffffu, s2, 2);
        d2 += __shfl_xor_sync(0xffffffffu, d2, 1); d2 += __shfl_xor_sync(0xffffffffu, d2, 2);
        if (lk == 0) {
            if (row1 < N) { asrcn[row1 * 8 + h] = s1; adstn[row1 * 8 + h] = d1; }
            if (row2 < N) { asrcn[row2 * 8 + h] = s2; adstn[row2 * 8 + h] = d2; }
        }
    }
}

// ----- GAT1 pull aggregation: warp per dst, unroll x2 ------------------------
__global__ void k_agg1(const int* __restrict__ rowptr, const int* __restrict__ esrc,
                       const float* __restrict__ asrc, const float* __restrict__ adst,
                       const float* __restrict__ h1, const float* __restrict__ b1,
                       float* __restrict__ out1, int N) {
    int d = (int)(((long long)blockIdx.x * blockDim.x + threadIdx.x) >> 5);
    int lane = threadIdx.x & 31;
    if (d >= N) return;
    int beg = rowptr[d], endp = rowptr[d + 1];
    float ad = (lane < 8) ? adst[d * 8 + lane] : 0.f;
    float den = 0.f;
    float4 acc0 = {0, 0, 0, 0}, acc1 = {0, 0, 0, 0};
    int h0 = lane >> 3;
    for (int base = beg; base < endp; base += 32) {
        int nn = min(32, endp - base);
        int sreg = (base + lane < endp) ? esrc[base + lane] : 0;
        int j = 0;
        for (; j + 1 < nn; j += 2) {
            int sA = __shfl_sync(0xffffffffu, sreg, j);
            int sB = __shfl_sync(0xffffffffu, sreg, j + 1);
            float wA = 0.f, wB = 0.f;
            if (lane < 8) {
                wA = __expf(lrelu(asrc[sA * 8 + lane] + ad));
                wB = __expf(lrelu(asrc[sB * 8 + lane] + ad));
            }
            den += wA + wB;
            float aA0 = __shfl_sync(0xffffffffu, wA, h0);
            float aA1 = __shfl_sync(0xffffffffu, wA, h0 + 4);
            float aB0 = __shfl_sync(0xffffffffu, wB, h0);
            float aB1 = __shfl_sync(0xffffffffu, wB, h0 + 4);
            const float4* hpA = reinterpret_cast<const float4*>(h1 + (size_t)sA * 256);
            const float4* hpB = reinterpret_cast<const float4*>(h1 + (size_t)sB * 256);
            float4 vA0 = hpA[lane], vA1 = hpA[lane + 32];
            float4 vB0 = hpB[lane], vB1 = hpB[lane + 32];
            acc0.x += vA0.x * aA0 + vB0.x * aB0;
            acc0.y += vA0.y * aA0 + vB0.y * aB0;
            acc0.z += vA0.z * aA0 + vB0.z * aB0;
            acc0.w += vA0.w * aA0 + vB0.w * aB0;
            acc1.x += vA1.x * aA1 + vB1.x * aB1;
            acc1.y += vA1.y * aA1 + vB1.y * aB1;
            acc1.z += vA1.z * aA1 + vB1.z * aB1;
            acc1.w += vA1.w * aA1 + vB1.w * aB1;
        }
        if (j < nn) {
            int s = __shfl_sync(0xffffffffu, sreg, j);
            float wgt = 0.f;
            if (lane < 8) wgt = __expf(lrelu(asrc[s * 8 + lane] + ad));
            den += wgt;
            float a0 = __shfl_sync(0xffffffffu, wgt, h0);
            float a1 = __shfl_sync(0xffffffffu, wgt, h0 + 4);
            const float4* hp = reinterpret_cast<const float4*>(h1 + (size_t)s * 256);
            float4 v0 = hp[lane], v1 = hp[lane + 32];
            acc0.x += v0.x * a0; acc0.y += v0.y * a0; acc0.z += v0.z * a0; acc0.w += v0.w * a0;
            acc1.x += v1.x * a1; acc1.y += v1.y * a1; acc1.z += v1.z * a1; acc1.w += v1.w * a1;
        }
    }
    float dn0 = __shfl_sync(0xffffffffu, den, h0);
    float dn1 = __shfl_sync(0xffffffffu, den, h0 + 4);
    float r0 = 1.f / dn0, r1 = 1.f / dn1;
    const float4* bp = reinterpret_cast<const float4*>(b1);
    float4 bb0 = bp[lane], bb1 = bp[lane + 32];
    float4 o0, o1;
    o0.x = eluf(acc0.x * r0 + bb0.x); o0.y = eluf(acc0.y * r0 + bb0.y);
    o0.z = eluf(acc0.z * r0 + bb0.z); o0.w = eluf(acc0.w * r0 + bb0.w);
    o1.x = eluf(acc1.x * r1 + bb1.x); o1.y = eluf(acc1.y * r1 + bb1.y);
    o1.z = eluf(acc1.z * r1 + bb1.z); o1.w = eluf(acc1.w * r1 + bb1.w);
    float4* op = reinterpret_cast<float4*>(out1 + (size_t)d * 256);
    op[lane] = o0;
    op[lane + 32] = o1;
}

// ----- GEMM2: h2 = x2[N,256] @ W2[256,16], fused alpha2 ----------------------
__global__ void k_gemm2(const float* __restrict__ x2, const float* __restrict__ W2,
                        const float* __restrict__ a_src2, const float* __restrict__ a_dst2,
                        float* __restrict__ h2, float* __restrict__ asrc2n,
                        float* __restrict__ adst2n, int N) {
    __shared__ float Wsh[256 * 16];
    int t = threadIdx.x;
    for (int i = t; i < 4096; i += 256) Wsh[i] = W2[i];
    __syncthreads();
    int n = blockIdx.x * 16 + (t >> 4);
    int c = t & 15;
    if (n >= N) return;
    float acc = 0.f;
    const float4* xr = reinterpret_cast<const float4*>(x2 + (size_t)n * 256);
#pragma unroll 8
    for (int k4 = 0; k4 < 64; k4++) {
        float4 xv = xr[k4];
        acc += xv.x * Wsh[(k4 * 4 + 0) * 16 + c] + xv.y * Wsh[(k4 * 4 + 1) * 16 + c]
             + xv.z * Wsh[(k4 * 4 + 2) * 16 + c] + xv.w * Wsh[(k4 * 4 + 3) * 16 + c];
    }
    h2[(size_t)n * 16 + c] = acc;
    float r1 = acc * a_src2[c];
    float r2 = acc * a_dst2[c];
#pragma unroll
    for (int m = 8; m >= 1; m >>= 1) {
        r1 += __shfl_xor_sync(0xffffffffu, r1, m, 16);
        r2 += __shfl_xor_sync(0xffffffffu, r2, m, 16);
    }
    if (c == 0) { asrc2n[n] = r1; adst2n[n] = r2; }
}

// ----- GAT2 pull aggregation: 4 lanes per dst ---------------------------------
__global__ void k_agg2(const int* __restrict__ rowptr, const int* __restrict__ esrc,
                       const float* __restrict__ asrc, const float* __restrict__ adst,
                       const float* __restrict__ h2, const float* __restrict__ b2,
                       float* __restrict__ out2, int N) {
    long long gt = (long long)blockIdx.x * blockDim.x + threadIdx.x;
    int d = (int)(gt >> 2);
    int q = threadIdx.x & 3;
    if (d >= N) return;
    int beg = rowptr[d], endp = rowptr[d + 1];
    float ad = adst[d];
    float den = 0.f;
    float4 acc = {0, 0, 0, 0};
    for (int idx = beg; idx < endp; idx++) {
        int s = esrc[idx];
        float wgt = __expf(lrelu(asrc[s] + ad));
        den += wgt;
        float4 v = reinterpret_cast<const float4*>(h2 + (size_t)s * 16)[q];
        acc.x += v.x * wgt; acc.y += v.y * wgt; acc.z += v.z * wgt; acc.w += v.w * wgt;
    }
    float r = 1.f / den;
    float4 bb = reinterpret_cast<const float4*>(b2)[q];
    float4 o;
    o.x = eluf(acc.x * r + bb.x); o.y = eluf(acc.y * r + bb.y);
    o.z = eluf(acc.z * r + bb.z); o.w = eluf(acc.w * r + bb.w);
    reinterpret_cast<float4*>(out2 + (size_t)d * 16)[q] = o;
}

// ----- GCN transform ----------------------------------------------------------
__global__ void k_h3(const float* __restrict__ x3, const float* __restrict__ W3,
                     const int* __restrict__ rowptr, float* __restrict__ g, int N) {
    __shared__ float Wsh[256];
    if (threadIdx.x < 256) Wsh[threadIdx.x] = W3[threadIdx.x];
    __syncthreads();
    int n = blockIdx.x * blockDim.x + threadIdx.x;
    if (n >= N) return;
    float xr[16];
    const float4* xp = reinterpret_cast<const float4*>(x3 + (size_t)n * 16);
#pragma unroll
    for (int j = 0; j < 4; j++) {
        float4 v = xp[j];
        xr[4 * j + 0] = v.x; xr[4 * j + 1] = v.y; xr[4 * j + 2] = v.z; xr[4 * j + 3] = v.w;
    }
    float dv = rsqrtf((float)(rowptr[n + 1] - rowptr[n]));
    float* go = g + (size_t)n * 16;
#pragma unroll
    for (int c = 0; c < 16; c++) {
        float acc = 0.f;
#pragma unroll
        for (int k = 0; k < 16; k++) acc += xr[k] * Wsh[k * 16 + c];
        go[c] = acc * dv;
    }
}

// ----- GCN pull aggregation + finalize ----------------------------------------
__global__ void k_agg3(const int* __restrict__ rowptr, const int* __restrict__ esrc,
                       const float* __restrict__ g, const float* __restrict__ b3,
                       float* __restrict__ out, int N) {
    long long gt = (long long)blockIdx.x * blockDim.x + threadIdx.x;
    int d = (int)(gt >> 2);
    int q = threadIdx.x & 3;
    if (d >= N) return;
    int beg = rowptr[d], endp = rowptr[d + 1];
    float4 acc = {0, 0, 0, 0};
    for (int idx = beg; idx < endp; idx++) {
        int s = esrc[idx];
        float4 v = reinterpret_cast<const float4*>(g + (size_t)s * 16)[q];
        acc.x += v.x; acc.y += v.y; acc.z += v.z; acc.w += v.w;
    }
    float dv = rsqrtf((float)(endp - beg));
    float4 bb = reinterpret_cast<const float4*>(b3)[q];
    float4 o;
    o.x = acc.x * dv + bb.x; o.y = acc.y * dv + bb.y;
    o.z = acc.z * dv + bb.z; o.w = acc.w * dv + bb.w;
    reinterpret_cast<float4*>(out + (size_t)d * 16)[q] = o;
}

// ---------------------------------------------------------------------------
extern "C" void kernel_launch(void* const* d_in, const int* in_sizes, int n_in,
                              void* d_out, int out_size) {
    const float* x      = (const float*)d_in[0];
    const int*   ei     = (const int*)d_in[1];
    const float* W1     = (const float*)d_in[2];
    const float* a_src1 = (const float*)d_in[3];
    const float* a_dst1 = (const float*)d_in[4];
    const float* b1     = (const float*)d_in[5];
    const float* W2     = (const float*)d_in[6];
    const float* a_src2 = (const float*)d_in[7];
    const float* a_dst2 = (const float*)d_in[8];
    const float* b2     = (const float*)d_in[9];
    const float* W3     = (const float*)d_in[10];
    const float* b3     = (const float*)d_in[11];
    float* out = (float*)d_out;

    const int N = in_sizes[0] / 128;
    const int E = in_sizes[1] / 2;
    const int ET = E + N;

    float *h1, *asrc1, *adst1, *out1, *h2, *asrc2, *adst2, *out2, *g;
    int *degi, *cursor, *rowptr, *esrc;
    float2 *xsp, *wsp;
    void* p;
    cudaGetSymbolAddress(&p, g_h1);     h1     = (float*)p;
    cudaGetSymbolAddress(&p, g_asrc1);  asrc1  = (float*)p;
    cudaGetSymbolAddress(&p, g_adst1);  adst1  = (float*)p;
    cudaGetSymbolAddress(&p, g_out1);   out1   = (float*)p;
    cudaGetSymbolAddress(&p, g_h2);     h2     = (float*)p;
    cudaGetSymbolAddress(&p, g_asrc2);  asrc2  = (float*)p;
    cudaGetSymbolAddress(&p, g_adst2);  adst2  = (float*)p;
    cudaGetSymbolAddress(&p, g_out2);   out2   = (float*)p;
    cudaGetSymbolAddress(&p, g_g);      g      = (float*)p;
    cudaGetSymbolAddress(&p, g_degi);   degi   = (int*)p;
    cudaGetSymbolAddress(&p, g_cursor); cursor = (int*)p;
    cudaGetSymbolAddress(&p, g_rowptr); rowptr = (int*)p;
    cudaGetSymbolAddress(&p, g_esrc);   esrc   = (int*)p;
    cudaGetSymbolAddress(&p, g_xsp);    xsp    = (float2*)p;
    cudaGetSymbolAddress(&p, g_wsp);    wsp    = (float2*)p;

    // one-time resource setup (host objects only; no device memory)
    static cudaStream_t s2 = nullptr;
    static cudaEvent_t evFork = nullptr, evJoin = nullptr;
    static int smem_set = 0;
    if (!s2) {
        cudaStreamCreateWithFlags(&s2, cudaStreamNonBlocking);
        cudaEventCreateWithFlags(&evFork, cudaEventDisableTiming);
        cudaEventCreateWithFlags(&evJoin, cudaEventDisableTiming);
    }
    if (!smem_set) {
        cudaFuncSetAttribute(k_gemm1_tc2,
                             cudaFuncAttributeMaxDynamicSharedMemorySize,
                             SMEM_F2 * (int)sizeof(float2));
        smem_set = 1;
    }

    const int B = 256;

    // ---- fork: CSR build chain on s2, concurrent with split+GEMM1 ----
    cudaEventRecord(evFork, 0);
    cudaStreamWaitEvent(s2, evFork, 0);

    cudaMemsetAsync(degi,   0, (size_t)N * sizeof(int), s2);
    cudaMemsetAsync(cursor, 0, (size_t)N * sizeof(int), s2);
    k_deg<<<(ET + B - 1) / B, B, 0, s2>>>(ei, E, N, degi);
    k_scan<<<1, 1024, 0, s2>>>(degi, rowptr, N, ET);
    k_fill<<<(ET + B - 1) / B, B, 0, s2>>>(ei, E, N, rowptr, cursor, esrc);
    cudaEventRecord(evJoin, s2);

    // main stream: pre-split + tensor-core GEMM1 (independent of CSR)
    k_split<<<(N * 32 + B - 1) / B, B>>>(x, xsp, N * 32);
    k_split<<<(8192 + B - 1) / B, B>>>(W1, wsp, 8192);
    {
        dim3 grid((N + 127) / 128, 2);
        k_gemm1_tc2<<<grid, 256, SMEM_F2 * sizeof(float2)>>>(
            xsp, wsp, a_src1, a_dst1, h1, asrc1, adst1, N);
    }

    // ---- join: agg1 needs both h1/alphas (stream 0) and esrc/rowptr (s2) ----
    cudaStreamWaitEvent(0, evJoin, 0);

    {
        long long tot = (long long)N * 32;   // warp per dst
        k_agg1<<<(unsigned)((tot + B - 1) / B), B>>>(rowptr, esrc, asrc1, adst1, h1, b1, out1, N);
    }

    // Layer 2: GAT(256 -> 16, 1 head)
    k_gemm2<<<(N + 15) / 16, B>>>(out1, W2, a_src2, a_dst2, h2, asrc2, adst2, N);
    {
        long long tot = (long long)N * 4;
        k_agg2<<<(unsigned)((tot + B - 1) / B), B>>>(rowptr, esrc, asrc2, adst2, h2, b2, out2, N);
    }

    // Layer 3: GCN(16 -> 16)
    k_h3<<<(N + B - 1) / B, B>>>(out2, W3, rowptr, g, N);
    {
        long long tot = (long long)N * 4;
        k_agg3<<<(unsigned)((tot + B - 1) / B), B>>>(rowptr, esrc, g, b3, out, N);
    }
}

// round 7
// speedup vs baseline: 2.1027x; 1.0543x over previous
#include <cuda_runtime.h>
#include <cuda_fp16.h>
#include <math.h>

#define NMAX 50000
#define EMAX 800000
#define ETMAX (EMAX + NMAX)

// ---------------- scratch (device globals) -----------------------------------
__device__ __half g_h1h[NMAX * 256];     // GAT1 features stored fp16 (gather payload)
__device__ float g_asrc1[NMAX * 8];
__device__ float g_adst1[NMAX * 8];
__device__ float g_out1[NMAX * 256];
__device__ float g_h2[NMAX * 16];
__device__ float g_asrc2[NMAX];
__device__ float g_adst2[NMAX];
__device__ float g_out2[NMAX * 16];
__device__ float g_g[NMAX * 16];
__device__ int   g_degi[NMAX];
__device__ int   g_cursor[NMAX];
__device__ int   g_rowptr[NMAX + 1];
__device__ int   g_esrc[ETMAX];
__device__ float2 g_xsp[NMAX * 128];     // x split into (hi,lo) tf32 pairs
__device__ float2 g_wsp[128 * 256];      // W1 split

__device__ __forceinline__ float lrelu(float x) { return x > 0.f ? x : 0.2f * x; }
__device__ __forceinline__ float eluf(float x) { return x > 0.f ? x : expm1f(x); }

// ---------------- CSR build ---------------------------------------------------
__global__ void k_deg(const int* __restrict__ ei, int E, int N, int* __restrict__ degi) {
    int e = blockIdx.x * blockDim.x + threadIdx.x;
    int ET = E + N;
    if (e >= ET) return;
    int d = (e < E) ? ei[E + e] : e - E;
    atomicAdd(&degi[d], 1);
}

__global__ void k_scan(const int* __restrict__ degi, int* __restrict__ rowptr,
                       int N, int ET) {
    __shared__ int sh[1024];
    int t = threadIdx.x;
    int chunk = (N + 1023) / 1024;
    int start = t * chunk;
    int end = min(start + chunk, N);
    int sum = 0;
    for (int i = start; i < end; i++) sum += degi[i];
    sh[t] = sum;
    __syncthreads();
    for (int off = 1; off < 1024; off <<= 1) {
        int v = (t >= off) ? sh[t - off] : 0;
        __syncthreads();
        sh[t] += v;
        __syncthreads();
    }
    int run = (t == 0) ? 0 : sh[t - 1];
    for (int i = start; i < end; i++) { rowptr[i] = run; run += degi[i]; }
    if (t == 1023) rowptr[N] = ET;
}

__global__ void k_fill(const int* __restrict__ ei, int E, int N,
                       const int* __restrict__ rowptr, int* __restrict__ cursor,
                       int* __restrict__ esrc) {
    int e = blockIdx.x * blockDim.x + threadIdx.x;
    int ET = E + N;
    if (e >= ET) return;
    int s, d;
    if (e < E) { s = ei[e]; d = ei[E + e]; } else { s = d = e - E; }
    int pos = rowptr[d] + atomicAdd(&cursor[d], 1);
    esrc[pos] = s;
}

// ---------------- tf32 helpers ------------------------------------------------
__device__ __forceinline__ float2 tf32split2(float x) {
    unsigned u;
    asm("cvt.rna.tf32.f32 %0, %1;" : "=r"(u) : "f"(x));
    float hi = __uint_as_float(u);
    float r = x - hi;
    unsigned ul;
    asm("cvt.rna.tf32.f32 %0, %1;" : "=r"(ul) : "f"(r));
    return make_float2(hi, __uint_as_float(ul));
}

__device__ __forceinline__ void mma_tf32(float* d, const unsigned* a, const unsigned* b) {
    asm volatile("mma.sync.aligned.m16n8k8.row.col.f32.tf32.tf32.f32 "
                 "{%0,%1,%2,%3}, {%4,%5,%6,%7}, {%8,%9}, {%0,%1,%2,%3};"
                 : "+f"(d[0]), "+f"(d[1]), "+f"(d[2]), "+f"(d[3])
                 : "r"(a[0]), "r"(a[1]), "r"(a[2]), "r"(a[3]),
                   "r"(b[0]), "r"(b[1]));
}

__device__ __forceinline__ void cpasync16(void* dst, const void* src) {
    unsigned d = (unsigned)__cvta_generic_to_shared(dst);
    asm volatile("cp.async.cg.shared.global [%0], [%1], 16;" :: "r"(d), "l"(src));
}

// ---------------- split pass: f32 -> interleaved (hi,lo) ----------------------
__global__ void k_split(const float* __restrict__ src, float2* __restrict__ dst,
                        int total4) {
    int i = blockIdx.x * blockDim.x + threadIdx.x;
    if (i >= total4) return;
    float4 v = reinterpret_cast<const float4*>(src)[i];
    float2 o0 = tf32split2(v.x), o1 = tf32split2(v.y);
    float2 o2 = tf32split2(v.z), o3 = tf32split2(v.w);
    float4* d = reinterpret_cast<float4*>(dst + (size_t)i * 4);
    d[0] = make_float4(o0.x, o0.y, o1.x, o1.y);
    d[1] = make_float4(o2.x, o2.y, o3.x, o3.y);
}

// ---------------- GEMM1 (tensor core, pre-split tf32, fused alpha) ------------
#define AS_STRIDE 20
#define AS_STAGE  (128 * AS_STRIDE)
#define BS_STRIDE 132
#define BS_STAGE  (16 * BS_STRIDE)
#define SMEM_F2   (2 * AS_STAGE + 2 * BS_STAGE)

__global__ __launch_bounds__(256) void k_gemm1_tc2(
        const float2* __restrict__ xsp, const float2* __restrict__ wsp,
        const float* __restrict__ a_src, const float* __restrict__ a_dst,
        __half* __restrict__ h1h, float* __restrict__ asrcn, float* __restrict__ adstn,
        int N) {
    extern __shared__ float2 smem[];
    const int t = threadIdx.x;
    const int warp = t >> 5, lane = t & 31;
    const int wm = warp >> 2, wn = warp & 3;
    const int lm = lane >> 2, lk = lane & 3;
    const int r0 = blockIdx.x * 128;
    const int n0 = blockIdx.y * 128;

    float acc[4][4][4];
#pragma unroll
    for (int i = 0; i < 4; i++)
#pragma unroll
        for (int j = 0; j < 4; j++)
#pragma unroll
            for (int v = 0; v < 4; v++) acc[i][j][v] = 0.f;

    auto issue = [&](int c, int buf) {
        int k0 = c * 16;
        float2* As = smem + buf * AS_STAGE;
        float2* Bs = smem + 2 * AS_STAGE + buf * BS_STAGE;
#pragma unroll
        for (int i = 0; i < 4; i++) {
            int op = t + i * 256;
            int row = op >> 3, seg = op & 7;
            int gr = r0 + row; if (gr > N - 1) gr = N - 1;
            cpasync16(As + row * AS_STRIDE + seg * 2,
                      xsp + (size_t)gr * 128 + k0 + seg * 2);
        }
#pragma unroll
        for (int i = 0; i < 4; i++) {
            int op = t + i * 256;
            int row = op >> 6, seg = op & 63;
            cpasync16(Bs + row * BS_STRIDE + seg * 2,
                      wsp + (size_t)(k0 + row) * 256 + n0 + seg * 2);
        }
        asm volatile("cp.async.commit_group;");
    };

    issue(0, 0);
    for (int c = 0; c < 8; c++) {
        int buf = c & 1;
        if (c < 7) {
            issue(c + 1, buf ^ 1);
            asm volatile("cp.async.wait_group 1;");
        } else {
            asm volatile("cp.async.wait_group 0;");
        }
        __syncthreads();
        const float2* As = smem + buf * AS_STAGE;
        const float2* Bs = smem + 2 * AS_STAGE + buf * BS_STAGE;
#pragma unroll
        for (int ks = 0; ks < 16; ks += 8) {
            unsigned Ah[4][4], Al[4][4];
#pragma unroll
            for (int mt = 0; mt < 4; mt++) {
                int mrow = wm * 64 + mt * 16 + lm;
                int c1 = ks + lk, c2 = c1 + 4;
                float2 p0 = As[mrow * AS_STRIDE + c1];
                float2 p1 = As[(mrow + 8) * AS_STRIDE + c1];
                float2 p2 = As[mrow * AS_STRIDE + c2];
                float2 p3 = As[(mrow + 8) * AS_STRIDE + c2];
                Ah[mt][0] = __float_as_uint(p0.x); Al[mt][0] = __float_as_uint(p0.y);
                Ah[mt][1] = __float_as_uint(p1.x); Al[mt][1] = __float_as_uint(p1.y);
                Ah[mt][2] = __float_as_uint(p2.x); Al[mt][2] = __float_as_uint(p2.y);
                Ah[mt][3] = __float_as_uint(p3.x); Al[mt][3] = __float_as_uint(p3.y);
            }
            unsigned Bh[4][2], Bl[4][2];
#pragma unroll
            for (int nt = 0; nt < 4; nt++) {
                int n = wn * 32 + nt * 8 + lm;
                float2 q0 = Bs[(ks + lk) * BS_STRIDE + n];
                float2 q1 = Bs[(ks + lk + 4) * BS_STRIDE + n];
                Bh[nt][0] = __float_as_uint(q0.x); Bl[nt][0] = __float_as_uint(q0.y);
                Bh[nt][1] = __float_as_uint(q1.x); Bl[nt][1] = __float_as_uint(q1.y);
            }
#pragma unroll
            for (int mt = 0; mt < 4; mt++)
#pragma unroll
                for (int nt = 0; nt < 4; nt++) {
                    mma_tf32(acc[mt][nt], Ah[mt], Bh[nt]);
                    mma_tf32(acc[mt][nt], Ah[mt], Bl[nt]);
                    mma_tf32(acc[mt][nt], Al[mt], Bh[nt]);
                }
        }
        __syncthreads();
    }

    const int h = blockIdx.y * 4 + wn;
    float2 asv[4], adv[4];
#pragma unroll
    for (int nt = 0; nt < 4; nt++) {
        asv[nt] = *reinterpret_cast<const float2*>(a_src + h * 32 + nt * 8 + lk * 2);
        adv[nt] = *reinterpret_cast<const float2*>(a_dst + h * 32 + nt * 8 + lk * 2);
    }
#pragma unroll
    for (int mt = 0; mt < 4; mt++) {
        int row1 = r0 + wm * 64 + mt * 16 + lm;
        int row2 = row1 + 8;
        float s1 = 0.f, d1 = 0.f, s2 = 0.f, d2 = 0.f;
#pragma unroll
        for (int nt = 0; nt < 4; nt++) {
            int col = n0 + wn * 32 + nt * 8 + lk * 2;
            s1 += acc[mt][nt][0] * asv[nt].x + acc[mt][nt][1] * asv[nt].y;
            d1 += acc[mt][nt][0] * adv[nt].x + acc[mt][nt][1] * adv[nt].y;
            s2 += acc[mt][nt][2] * asv[nt].x + acc[mt][nt][3] * asv[nt].y;
            d2 += acc[mt][nt][2] * adv[nt].x + acc[mt][nt][3] * adv[nt].y;
            if (row1 < N)
                *reinterpret_cast<__half2*>(h1h + (size_t)row1 * 256 + col) =
                    __floats2half2_rn(acc[mt][nt][0], acc[mt][nt][1]);
            if (row2 < N)
                *reinterpret_cast<__half2*>(h1h + (size_t)row2 * 256 + col) =
                    __floats2half2_rn(acc[mt][nt][2], acc[mt][nt][3]);
        }
        s1 += __shfl_xor_sync(0xffffffffu, s1, 1); s1 += __shfl_xor_sync(0xffffffffu, s1, 2);
        d1 += __shfl_xor_sync(0xffffffffu, d1, 1); d1 += __shfl_xor_sync(0xffffffffu, d1, 2);
        s2 += __shfl_xor_sync(0xffffffffu, s2, 1); s2 += __shfl_xor_sync(0xffffffffu, s2, 2);
        d2 += __shfl_xor_sync(0xffffffffu, d2, 1); d2 += __shfl_xor_sync(0xffffffffu, d2, 2);
        if (lk == 0) {
            if (row1 < N) { asrcn[row1 * 8 + h] = s1; adstn[row1 * 8 + h] = d1; }
            if (row2 < N) { asrcn[row2 * 8 + h] = s2; adstn[row2 * 8 + h] = d2; }
        }
    }
}

// ----- GAT1 pull aggregation: warp per dst, fp16 gather, unroll x2 -----------
__global__ void k_agg1(const int* __restrict__ rowptr, const int* __restrict__ esrc,
                       const float* __restrict__ asrc, const float* __restrict__ adst,
                       const __half* __restrict__ h1h, const float* __restrict__ b1,
                       float* __restrict__ out1, int N) {
    int d = (int)(((long long)blockIdx.x * blockDim.x + threadIdx.x) >> 5);
    int lane = threadIdx.x & 31;
    if (d >= N) return;
    int beg = rowptr[d], endp = rowptr[d + 1];
    float ad = (lane < 8) ? adst[d * 8 + lane] : 0.f;
    float den = 0.f;
    float accv[8];
#pragma unroll
    for (int i = 0; i < 8; i++) accv[i] = 0.f;
    const int h0 = lane >> 2;                 // head owning this lane's 8 cols
    for (int base = beg; base < endp; base += 32) {
        int nn = min(32, endp - base);
        int sreg = (base + lane < endp) ? esrc[base + lane] : 0;
        int j = 0;
        for (; j + 1 < nn; j += 2) {
            int sA = __shfl_sync(0xffffffffu, sreg, j);
            int sB = __shfl_sync(0xffffffffu, sreg, j + 1);
            float wA = 0.f, wB = 0.f;
            if (lane < 8) {
                wA = __expf(lrelu(asrc[sA * 8 + lane] + ad));
                wB = __expf(lrelu(asrc[sB * 8 + lane] + ad));
            }
            den += wA + wB;
            float aA = __shfl_sync(0xffffffffu, wA, h0);
            float aB = __shfl_sync(0xffffffffu, wB, h0);
            uint4 rA = *reinterpret_cast<const uint4*>(h1h + (size_t)sA * 256 + lane * 8);
            uint4 rB = *reinterpret_cast<const uint4*>(h1h + (size_t)sB * 256 + lane * 8);
            float2 fA0 = __half22float2(*reinterpret_cast<__half2*>(&rA.x));
            float2 fA1 = __half22float2(*reinterpret_cast<__half2*>(&rA.y));
            float2 fA2 = __half22float2(*reinterpret_cast<__half2*>(&rA.z));
            float2 fA3 = __half22float2(*reinterpret_cast<__half2*>(&rA.w));
            float2 fB0 = __half22float2(*reinterpret_cast<__half2*>(&rB.x));
            float2 fB1 = __half22float2(*reinterpret_cast<__half2*>(&rB.y));
            float2 fB2 = __half22float2(*reinterpret_cast<__half2*>(&rB.z));
            float2 fB3 = __half22float2(*reinterpret_cast<__half2*>(&rB.w));
            accv[0] += fA0.x * aA + fB0.x * aB;
            accv[1] += fA0.y * aA + fB0.y * aB;
            accv[2] += fA1.x * aA + fB1.x * aB;
            accv[3] += fA1.y * aA + fB1.y * aB;
            accv[4] += fA2.x * aA + fB2.x * aB;
            accv[5] += fA2.y * aA + fB2.y * aB;
            accv[6] += fA3.x * aA + fB3.x * aB;
            accv[7] += fA3.y * aA + fB3.y * aB;
        }
        if (j < nn) {
            int s = __shfl_sync(0xffffffffu, sreg, j);
            float wgt = 0.f;
            if (lane < 8) wgt = __expf(lrelu(asrc[s * 8 + lane] + ad));
            den += wgt;
            float a = __shfl_sync(0xffffffffu, wgt, h0);
            uint4 r = *reinterpret_cast<const uint4*>(h1h + (size_t)s * 256 + lane * 8);
            float2 f0 = __half22float2(*reinterpret_cast<__half2*>(&r.x));
            float2 f1 = __half22float2(*reinterpret_cast<__half2*>(&r.y));
            float2 f2 = __half22float2(*reinterpret_cast<__half2*>(&r.z));
            float2 f3 = __half22float2(*reinterpret_cast<__half2*>(&r.w));
            accv[0] += f0.x * a; accv[1] += f0.y * a;
            accv[2] += f1.x * a; accv[3] += f1.y * a;
            accv[4] += f2.x * a; accv[5] += f2.y * a;
            accv[6] += f3.x * a; accv[7] += f3.y * a;
        }
    }
    float dn = __shfl_sync(0xffffffffu, den, h0);
    float rs = 1.f / dn;
    const float4* bp = reinterpret_cast<const float4*>(b1 + lane * 8);
    float4 bb0 = bp[0], bb1 = bp[1];
    float4 o0, o1;
    o0.x = eluf(accv[0] * rs + bb0.x); o0.y = eluf(accv[1] * rs + bb0.y);
    o0.z = eluf(accv[2] * rs + bb0.z); o0.w = eluf(accv[3] * rs + bb0.w);
    o1.x = eluf(accv[4] * rs + bb1.x); o1.y = eluf(accv[5] * rs + bb1.y);
    o1.z = eluf(accv[6] * rs + bb1.z); o1.w = eluf(accv[7] * rs + bb1.w);
    float4* op = reinterpret_cast<float4*>(out1 + (size_t)d * 256 + lane * 8);
    op[0] = o0;
    op[1] = o1;
}

// ----- GEMM2: h2 = x2[N,256] @ W2[256,16], fused alpha2 ----------------------
__global__ void k_gemm2(const float* __restrict__ x2, const float* __restrict__ W2,
                        const float* __restrict__ a_src2, const float* __restrict__ a_dst2,
                        float* __restrict__ h2, float* __restrict__ asrc2n,
                        float* __restrict__ adst2n, int N) {
    __shared__ float Wsh[256 * 16];
    int t = threadIdx.x;
    for (int i = t; i < 4096; i += 256) Wsh[i] = W2[i];
    __syncthreads();
    int n = blockIdx.x * 16 + (t >> 4);
    int c = t & 15;
    if (n >= N) return;
    float acc = 0.f;
    const float4* xr = reinterpret_cast<const float4*>(x2 + (size_t)n * 256);
#pragma unroll 8
    for (int k4 = 0; k4 < 64; k4++) {
        float4 xv = xr[k4];
        acc += xv.x * Wsh[(k4 * 4 + 0) * 16 + c] + xv.y * Wsh[(k4 * 4 + 1) * 16 + c]
             + xv.z * Wsh[(k4 * 4 + 2) * 16 + c] + xv.w * Wsh[(k4 * 4 + 3) * 16 + c];
    }
    h2[(size_t)n * 16 + c] = acc;
    float r1 = acc * a_src2[c];
    float r2 = acc * a_dst2[c];
#pragma unroll
    for (int m = 8; m >= 1; m >>= 1) {
        r1 += __shfl_xor_sync(0xffffffffu, r1, m, 16);
        r2 += __shfl_xor_sync(0xffffffffu, r2, m, 16);
    }
    if (c == 0) { asrc2n[n] = r1; adst2n[n] = r2; }
}

// ----- GAT2 pull aggregation: 4 lanes per dst ---------------------------------
__global__ void k_agg2(const int* __restrict__ rowptr, const int* __restrict__ esrc,
                       const float* __restrict__ asrc, const float* __restrict__ adst,
                       const float* __restrict__ h2, const float* __restrict__ b2,
                       float* __restrict__ out2, int N) {
    long long gt = (long long)blockIdx.x * blockDim.x + threadIdx.x;
    int d = (int)(gt >> 2);
    int q = threadIdx.x & 3;
    if (d >= N) return;
    int beg = rowptr[d], endp = rowptr[d + 1];
    float ad = adst[d];
    float den = 0.f;
    float4 acc = {0, 0, 0, 0};
    for (int idx = beg; idx < endp; idx++) {
        int s = esrc[idx];
        float wgt = __expf(lrelu(asrc[s] + ad));
        den += wgt;
        float4 v = reinterpret_cast<const float4*>(h2 + (size_t)s * 16)[q];
        acc.x += v.x * wgt; acc.y += v.y * wgt; acc.z += v.z * wgt; acc.w += v.w * wgt;
    }
    float r = 1.f / den;
    float4 bb = reinterpret_cast<const float4*>(b2)[q];
    float4 o;
    o.x = eluf(acc.x * r + bb.x); o.y = eluf(acc.y * r + bb.y);
    o.z = eluf(acc.z * r + bb.z); o.w = eluf(acc.w * r + bb.w);
    reinterpret_cast<float4*>(out2 + (size_t)d * 16)[q] = o;
}

// ----- GCN transform ----------------------------------------------------------
__global__ void k_h3(const float* __restrict__ x3, const float* __restrict__ W3,
                     const int* __restrict__ rowptr, float* __restrict__ g, int N) {
    __shared__ float Wsh[256];
    if (threadIdx.x < 256) Wsh[threadIdx.x] = W3[threadIdx.x];
    __syncthreads();
    int n = blockIdx.x * blockDim.x + threadIdx.x;
    if (n >= N) return;
    float xr[16];
    const float4* xp = reinterpret_cast<const float4*>(x3 + (size_t)n * 16);
#pragma unroll
    for (int j = 0; j < 4; j++) {
        float4 v = xp[j];
        xr[4 * j + 0] = v.x; xr[4 * j + 1] = v.y; xr[4 * j + 2] = v.z; xr[4 * j + 3] = v.w;
    }
    float dv = rsqrtf((float)(rowptr[n + 1] - rowptr[n]));
    float* go = g + (size_t)n * 16;
#pragma unroll
    for (int c = 0; c < 16; c++) {
        float acc = 0.f;
#pragma unroll
        for (int k = 0; k < 16; k++) acc += xr[k] * Wsh[k * 16 + c];
        go[c] = acc * dv;
    }
}

// ----- GCN pull aggregation + finalize ----------------------------------------
__global__ void k_agg3(const int* __restrict__ rowptr, const int* __restrict__ esrc,
                       const float* __restrict__ g, const float* __restrict__ b3,
                       float* __restrict__ out, int N) {
    long long gt = (long long)blockIdx.x * blockDim.x + threadIdx.x;
    int d = (int)(gt >> 2);
    int q = threadIdx.x & 3;
    if (d >= N) return;
    int beg = rowptr[d], endp = rowptr[d + 1];
    float4 acc = {0, 0, 0, 0};
    for (int idx = beg; idx < endp; idx++) {
        int s = esrc[idx];
        float4 v = reinterpret_cast<const float4*>(g + (size_t)s * 16)[q];
        acc.x += v.x; acc.y += v.y; acc.z += v.z; acc.w += v.w;
    }
    float dv = rsqrtf((float)(endp - beg));
    float4 bb = reinterpret_cast<const float4*>(b3)[q];
    float4 o;
    o.x = acc.x * dv + bb.x; o.y = acc.y * dv + bb.y;
    o.z = acc.z * dv + bb.z; o.w = acc.w * dv + bb.w;
    reinterpret_cast<float4*>(out + (size_t)d * 16)[q] = o;
}

// ---------------------------------------------------------------------------
extern "C" void kernel_launch(void* const* d_in, const int* in_sizes, int n_in,
                              void* d_out, int out_size) {
    const float* x      = (const float*)d_in[0];
    const int*   ei     = (const int*)d_in[1];
    const float* W1     = (const float*)d_in[2];
    const float* a_src1 = (const float*)d_in[3];
    const float* a_dst1 = (const float*)d_in[4];
    const float* b1     = (const float*)d_in[5];
    const float* W2     = (const float*)d_in[6];
    const float* a_src2 = (const float*)d_in[7];
    const float* a_dst2 = (const float*)d_in[8];
    const float* b2     = (const float*)d_in[9];
    const float* W3     = (const float*)d_in[10];
    const float* b3     = (const float*)d_in[11];
    float* out = (float*)d_out;

    const int N = in_sizes[0] / 128;
    const int E = in_sizes[1] / 2;
    const int ET = E + N;

    float *asrc1, *adst1, *out1, *h2, *asrc2, *adst2, *out2, *g;
    __half *h1h;
    int *degi, *cursor, *rowptr, *esrc;
    float2 *xsp, *wsp;
    void* p;
    cudaGetSymbolAddress(&p, g_h1h);    h1h    = (__half*)p;
    cudaGetSymbolAddress(&p, g_asrc1);  asrc1  = (float*)p;
    cudaGetSymbolAddress(&p, g_adst1);  adst1  = (float*)p;
    cudaGetSymbolAddress(&p, g_out1);   out1   = (float*)p;
    cudaGetSymbolAddress(&p, g_h2);     h2     = (float*)p;
    cudaGetSymbolAddress(&p, g_asrc2);  asrc2  = (float*)p;
    cudaGetSymbolAddress(&p, g_adst2);  adst2  = (float*)p;
    cudaGetSymbolAddress(&p, g_out2);   out2   = (float*)p;
    cudaGetSymbolAddress(&p, g_g);      g      = (float*)p;
    cudaGetSymbolAddress(&p, g_degi);   degi   = (int*)p;
    cudaGetSymbolAddress(&p, g_cursor); cursor = (int*)p;
    cudaGetSymbolAddress(&p, g_rowptr); rowptr = (int*)p;
    cudaGetSymbolAddress(&p, g_esrc);   esrc   = (int*)p;
    cudaGetSymbolAddress(&p, g_xsp);    xsp    = (float2*)p;
    cudaGetSymbolAddress(&p, g_wsp);    wsp    = (float2*)p;

    static cudaStream_t s2 = nullptr;
    static cudaEvent_t evFork = nullptr, evJoin = nullptr;
    static int smem_set = 0;
    if (!s2) {
        cudaStreamCreateWithFlags(&s2, cudaStreamNonBlocking);
        cudaEventCreateWithFlags(&evFork, cudaEventDisableTiming);
        cudaEventCreateWithFlags(&evJoin, cudaEventDisableTiming);
    }
    if (!smem_set) {
        cudaFuncSetAttribute(k_gemm1_tc2,
                             cudaFuncAttributeMaxDynamicSharedMemorySize,
                             SMEM_F2 * (int)sizeof(float2));
        smem_set = 1;
    }

    const int B = 256;

    // ---- fork: CSR build chain on s2, concurrent with split+GEMM1 ----
    cudaEventRecord(evFork, 0);
    cudaStreamWaitEvent(s2, evFork, 0);

    cudaMemsetAsync(degi,   0, (size_t)N * sizeof(int), s2);
    cudaMemsetAsync(cursor, 0, (size_t)N * sizeof(int), s2);
    k_deg<<<(ET + B - 1) / B, B, 0, s2>>>(ei, E, N, degi);
    k_scan<<<1, 1024, 0, s2>>>(degi, rowptr, N, ET);
    k_fill<<<(ET + B - 1) / B, B, 0, s2>>>(ei, E, N, rowptr, cursor, esrc);
    cudaEventRecord(evJoin, s2);

    // main stream: pre-split + tensor-core GEMM1
    k_split<<<(N * 32 + B - 1) / B, B>>>(x, xsp, N * 32);
    k_split<<<(8192 + B - 1) / B, B>>>(W1, wsp, 8192);
    {
        dim3 grid((N + 127) / 128, 2);
        k_gemm1_tc2<<<grid, 256, SMEM_F2 * sizeof(float2)>>>(
            xsp, wsp, a_src1, a_dst1, h1h, asrc1, adst1, N);
    }

    // ---- join ----
    cudaStreamWaitEvent(0, evJoin, 0);

    {
        long long tot = (long long)N * 32;   // warp per dst
        k_agg1<<<(unsigned)((tot + B - 1) / B), B>>>(rowptr, esrc, asrc1, adst1, h1h, b1, out1, N);
    }

    // Layer 2: GAT(256 -> 16, 1 head)
    k_gemm2<<<(N + 15) / 16, B>>>(out1, W2, a_src2, a_dst2, h2, asrc2, adst2, N);
    {
        long long tot = (long long)N * 4;
        k_agg2<<<(unsigned)((tot + B - 1) / B), B>>>(rowptr, esrc, asrc2, adst2, h2, b2, out2, N);
    }

    // Layer 3: GCN(16 -> 16)
    k_h3<<<(N + B - 1) / B, B>>>(out2, W3, rowptr, g, N);
    {
        long long tot = (long long)N * 4;
        k_agg3<<<(unsigned)((tot + B - 1) / B), B>>>(rowptr, esrc, g, b3, out, N);
    }
}

// round 8
// speedup vs baseline: 2.1700x; 1.0320x over previous
#include <cuda_runtime.h>
#include <cuda_fp16.h>
#include <math.h>

#define NMAX 50000
#define EMAX 800000
#define ETMAX (EMAX + NMAX)

// ---------------- scratch (device globals) -----------------------------------
__device__ __half g_h1h[NMAX * 256];     // GAT1 features fp16 (gather payload)
__device__ float g_asrc1[NMAX * 8];
__device__ float g_adst1[NMAX * 8];
__device__ __half g_out1h[NMAX * 256];   // GAT1 output (post ELU), fp16
__device__ __half g_h2h[NMAX * 16];      // GAT2 features fp16
__device__ float g_asrc2[NMAX];
__device__ float g_adst2[NMAX];
__device__ __half g_gh[NMAX * 16];       // GCN per-src message fp16
__device__ int   g_degi[NMAX];
__device__ int   g_cursor[NMAX];
__device__ int   g_rowptr[NMAX + 1];
__device__ int   g_esrc[ETMAX];
__device__ float2 g_xsp[NMAX * 128];     // x split into (hi,lo) tf32 pairs
__device__ float2 g_wsp[128 * 256];      // W1 split

__device__ __forceinline__ float lrelu(float x) { return x > 0.f ? x : 0.2f * x; }
__device__ __forceinline__ float eluf(float x) { return x > 0.f ? x : expm1f(x); }

// ---------------- CSR build ---------------------------------------------------
__global__ void k_deg(const int* __restrict__ ei, int E, int N, int* __restrict__ degi) {
    int e = blockIdx.x * blockDim.x + threadIdx.x;
    int ET = E + N;
    if (e >= ET) return;
    int d = (e < E) ? ei[E + e] : e - E;
    atomicAdd(&degi[d], 1);
}

__global__ void k_scan(const int* __restrict__ degi, int* __restrict__ rowptr,
                       int N, int ET) {
    __shared__ int sh[1024];
    int t = threadIdx.x;
    int chunk = (N + 1023) / 1024;
    int start = t * chunk;
    int end = min(start + chunk, N);
    int sum = 0;
    for (int i = start; i < end; i++) sum += degi[i];
    sh[t] = sum;
    __syncthreads();
    for (int off = 1; off < 1024; off <<= 1) {
        int v = (t >= off) ? sh[t - off] : 0;
        __syncthreads();
        sh[t] += v;
        __syncthreads();
    }
    int run = (t == 0) ? 0 : sh[t - 1];
    for (int i = start; i < end; i++) { rowptr[i] = run; run += degi[i]; }
    if (t == 1023) rowptr[N] = ET;
}

__global__ void k_fill(const int* __restrict__ ei, int E, int N,
                       const int* __restrict__ rowptr, int* __restrict__ cursor,
                       int* __restrict__ esrc) {
    int e = blockIdx.x * blockDim.x + threadIdx.x;
    int ET = E + N;
    if (e >= ET) return;
    int s, d;
    if (e < E) { s = ei[e]; d = ei[E + e]; } else { s = d = e - E; }
    int pos = rowptr[d] + atomicAdd(&cursor[d], 1);
    esrc[pos] = s;
}

// ---------------- tf32 helpers ------------------------------------------------
__device__ __forceinline__ float2 tf32split2(float x) {
    unsigned u;
    asm("cvt.rna.tf32.f32 %0, %1;" : "=r"(u) : "f"(x));
    float hi = __uint_as_float(u);
    float r = x - hi;
    unsigned ul;
    asm("cvt.rna.tf32.f32 %0, %1;" : "=r"(ul) : "f"(r));
    return make_float2(hi, __uint_as_float(ul));
}

__device__ __forceinline__ void mma_tf32(float* d, const unsigned* a, const unsigned* b) {
    asm volatile("mma.sync.aligned.m16n8k8.row.col.f32.tf32.tf32.f32 "
                 "{%0,%1,%2,%3}, {%4,%5,%6,%7}, {%8,%9}, {%0,%1,%2,%3};"
                 : "+f"(d[0]), "+f"(d[1]), "+f"(d[2]), "+f"(d[3])
                 : "r"(a[0]), "r"(a[1]), "r"(a[2]), "r"(a[3]),
                   "r"(b[0]), "r"(b[1]));
}

__device__ __forceinline__ void cpasync16(void* dst, const void* src) {
    unsigned d = (unsigned)__cvta_generic_to_shared(dst);
    asm volatile("cp.async.cg.shared.global [%0], [%1], 16;" :: "r"(d), "l"(src));
}

// ---------------- split pass: f32 -> interleaved (hi,lo) ----------------------
__global__ void k_split(const float* __restrict__ src, float2* __restrict__ dst,
                        int total4) {
    int i = blockIdx.x * blockDim.x + threadIdx.x;
    if (i >= total4) return;
    float4 v = reinterpret_cast<const float4*>(src)[i];
    float2 o0 = tf32split2(v.x), o1 = tf32split2(v.y);
    float2 o2 = tf32split2(v.z), o3 = tf32split2(v.w);
    float4* d = reinterpret_cast<float4*>(dst + (size_t)i * 4);
    d[0] = make_float4(o0.x, o0.y, o1.x, o1.y);
    d[1] = make_float4(o2.x, o2.y, o3.x, o3.y);
}

// ---------------- GEMM1 (tensor core, pre-split tf32, fused alpha) ------------
#define AS_STRIDE 20
#define AS_STAGE  (128 * AS_STRIDE)
#define BS_STRIDE 132
#define BS_STAGE  (16 * BS_STRIDE)
#define SMEM_F2   (2 * AS_STAGE + 2 * BS_STAGE)

__global__ __launch_bounds__(256) void k_gemm1_tc2(
        const float2* __restrict__ xsp, const float2* __restrict__ wsp,
        const float* __restrict__ a_src, const float* __restrict__ a_dst,
        __half* __restrict__ h1h, float* __restrict__ asrcn, float* __restrict__ adstn,
        int N) {
    extern __shared__ float2 smem[];
    const int t = threadIdx.x;
    const int warp = t >> 5, lane = t & 31;
    const int wm = warp >> 2, wn = warp & 3;
    const int lm = lane >> 2, lk = lane & 3;
    const int r0 = blockIdx.x * 128;
    const int n0 = blockIdx.y * 128;

    float acc[4][4][4];
#pragma unroll
    for (int i = 0; i < 4; i++)
#pragma unroll
        for (int j = 0; j < 4; j++)
#pragma unroll
            for (int v = 0; v < 4; v++) acc[i][j][v] = 0.f;

    auto issue = [&](int c, int buf) {
        int k0 = c * 16;
        float2* As = smem + buf * AS_STAGE;
        float2* Bs = smem + 2 * AS_STAGE + buf * BS_STAGE;
#pragma unroll
        for (int i = 0; i < 4; i++) {
            int op = t + i * 256;
            int row = op >> 3, seg = op & 7;
            int gr = r0 + row; if (gr > N - 1) gr = N - 1;
            cpasync16(As + row * AS_STRIDE + seg * 2,
                      xsp + (size_t)gr * 128 + k0 + seg * 2);
        }
#pragma unroll
        for (int i = 0; i < 4; i++) {
            int op = t + i * 256;
            int row = op >> 6, seg = op & 63;
            cpasync16(Bs + row * BS_STRIDE + seg * 2,
                      wsp + (size_t)(k0 + row) * 256 + n0 + seg * 2);
        }
        asm volatile("cp.async.commit_group;");
    };

    issue(0, 0);
    for (int c = 0; c < 8; c++) {
        int buf = c & 1;
        if (c < 7) {
            issue(c + 1, buf ^ 1);
            asm volatile("cp.async.wait_group 1;");
        } else {
            asm volatile("cp.async.wait_group 0;");
        }
        __syncthreads();
        const float2* As = smem + buf * AS_STAGE;
        const float2* Bs = smem + 2 * AS_STAGE + buf * BS_STAGE;
#pragma unroll
        for (int ks = 0; ks < 16; ks += 8) {
            unsigned Ah[4][4], Al[4][4];
#pragma unroll
            for (int mt = 0; mt < 4; mt++) {
                int mrow = wm * 64 + mt * 16 + lm;
                int c1 = ks + lk, c2 = c1 + 4;
                float2 p0 = As[mrow * AS_STRIDE + c1];
                float2 p1 = As[(mrow + 8) * AS_STRIDE + c1];
                float2 p2 = As[mrow * AS_STRIDE + c2];
                float2 p3 = As[(mrow + 8) * AS_STRIDE + c2];
                Ah[mt][0] = __float_as_uint(p0.x); Al[mt][0] = __float_as_uint(p0.y);
                Ah[mt][1] = __float_as_uint(p1.x); Al[mt][1] = __float_as_uint(p1.y);
                Ah[mt][2] = __float_as_uint(p2.x); Al[mt][2] = __float_as_uint(p2.y);
                Ah[mt][3] = __float_as_uint(p3.x); Al[mt][3] = __float_as_uint(p3.y);
            }
            unsigned Bh[4][2], Bl[4][2];
#pragma unroll
            for (int nt = 0; nt < 4; nt++) {
                int n = wn * 32 + nt * 8 + lm;
                float2 q0 = Bs[(ks + lk) * BS_STRIDE + n];
                float2 q1 = Bs[(ks + lk + 4) * BS_STRIDE + n];
                Bh[nt][0] = __float_as_uint(q0.x); Bl[nt][0] = __float_as_uint(q0.y);
                Bh[nt][1] = __float_as_uint(q1.x); Bl[nt][1] = __float_as_uint(q1.y);
            }
#pragma unroll
            for (int mt = 0; mt < 4; mt++)
#pragma unroll
                for (int nt = 0; nt < 4; nt++) {
                    mma_tf32(acc[mt][nt], Ah[mt], Bh[nt]);
                    mma_tf32(acc[mt][nt], Ah[mt], Bl[nt]);
                    mma_tf32(acc[mt][nt], Al[mt], Bh[nt]);
                }
        }
        __syncthreads();
    }

    const int h = blockIdx.y * 4 + wn;
    float2 asv[4], adv[4];
#pragma unroll
    for (int nt = 0; nt < 4; nt++) {
        asv[nt] = *reinterpret_cast<const float2*>(a_src + h * 32 + nt * 8 + lk * 2);
        adv[nt] = *reinterpret_cast<const float2*>(a_dst + h * 32 + nt * 8 + lk * 2);
    }
#pragma unroll
    for (int mt = 0; mt < 4; mt++) {
        int row1 = r0 + wm * 64 + mt * 16 + lm;
        int row2 = row1 + 8;
        float s1 = 0.f, d1 = 0.f, s2 = 0.f, d2 = 0.f;
#pragma unroll
        for (int nt = 0; nt < 4; nt++) {
            int col = n0 + wn * 32 + nt * 8 + lk * 2;
            s1 += acc[mt][nt][0] * asv[nt].x + acc[mt][nt][1] * asv[nt].y;
            d1 += acc[mt][nt][0] * adv[nt].x + acc[mt][nt][1] * adv[nt].y;
            s2 += acc[mt][nt][2] * asv[nt].x + acc[mt][nt][3] * asv[nt].y;
            d2 += acc[mt][nt][2] * adv[nt].x + acc[mt][nt][3] * adv[nt].y;
            if (row1 < N)
                *reinterpret_cast<__half2*>(h1h + (size_t)row1 * 256 + col) =
                    __floats2half2_rn(acc[mt][nt][0], acc[mt][nt][1]);
            if (row2 < N)
                *reinterpret_cast<__half2*>(h1h + (size_t)row2 * 256 + col) =
                    __floats2half2_rn(acc[mt][nt][2], acc[mt][nt][3]);
        }
        s1 += __shfl_xor_sync(0xffffffffu, s1, 1); s1 += __shfl_xor_sync(0xffffffffu, s1, 2);
        d1 += __shfl_xor_sync(0xffffffffu, d1, 1); d1 += __shfl_xor_sync(0xffffffffu, d1, 2);
        s2 += __shfl_xor_sync(0xffffffffu, s2, 1); s2 += __shfl_xor_sync(0xffffffffu, s2, 2);
        d2 += __shfl_xor_sync(0xffffffffu, d2, 1); d2 += __shfl_xor_sync(0xffffffffu, d2, 2);
        if (lk == 0) {
            if (row1 < N) { asrcn[row1 * 8 + h] = s1; adstn[row1 * 8 + h] = d1; }
            if (row2 < N) { asrcn[row2 * 8 + h] = s2; adstn[row2 * 8 + h] = d2; }
        }
    }
}

// ----- GAT1 pull aggregation: warp per dst, fp16 in/out ----------------------
__global__ void k_agg1(const int* __restrict__ rowptr, const int* __restrict__ esrc,
                       const float* __restrict__ asrc, const float* __restrict__ adst,
                       const __half* __restrict__ h1h, const float* __restrict__ b1,
                       __half* __restrict__ out1h, int N) {
    int d = (int)(((long long)blockIdx.x * blockDim.x + threadIdx.x) >> 5);
    int lane = threadIdx.x & 31;
    if (d >= N) return;
    int beg = rowptr[d], endp = rowptr[d + 1];
    float ad = (lane < 8) ? adst[d * 8 + lane] : 0.f;
    float den = 0.f;
    float accv[8];
#pragma unroll
    for (int i = 0; i < 8; i++) accv[i] = 0.f;
    const int h0 = lane >> 2;
    for (int base = beg; base < endp; base += 32) {
        int nn = min(32, endp - base);
        int sreg = (base + lane < endp) ? esrc[base + lane] : 0;
        int j = 0;
        for (; j + 1 < nn; j += 2) {
            int sA = __shfl_sync(0xffffffffu, sreg, j);
            int sB = __shfl_sync(0xffffffffu, sreg, j + 1);
            float wA = 0.f, wB = 0.f;
            if (lane < 8) {
                wA = __expf(lrelu(asrc[sA * 8 + lane] + ad));
                wB = __expf(lrelu(asrc[sB * 8 + lane] + ad));
            }
            den += wA + wB;
            float aA = __shfl_sync(0xffffffffu, wA, h0);
            float aB = __shfl_sync(0xffffffffu, wB, h0);
            uint4 rA = *reinterpret_cast<const uint4*>(h1h + (size_t)sA * 256 + lane * 8);
            uint4 rB = *reinterpret_cast<const uint4*>(h1h + (size_t)sB * 256 + lane * 8);
            float2 fA0 = __half22float2(*reinterpret_cast<__half2*>(&rA.x));
            float2 fA1 = __half22float2(*reinterpret_cast<__half2*>(&rA.y));
            float2 fA2 = __half22float2(*reinterpret_cast<__half2*>(&rA.z));
            float2 fA3 = __half22float2(*reinterpret_cast<__half2*>(&rA.w));
            float2 fB0 = __half22float2(*reinterpret_cast<__half2*>(&rB.x));
            float2 fB1 = __half22float2(*reinterpret_cast<__half2*>(&rB.y));
            float2 fB2 = __half22float2(*reinterpret_cast<__half2*>(&rB.z));
            float2 fB3 = __half22float2(*reinterpret_cast<__half2*>(&rB.w));
            accv[0] += fA0.x * aA + fB0.x * aB;
            accv[1] += fA0.y * aA + fB0.y * aB;
            accv[2] += fA1.x * aA + fB1.x * aB;
            accv[3] += fA1.y * aA + fB1.y * aB;
            accv[4] += fA2.x * aA + fB2.x * aB;
            accv[5] += fA2.y * aA + fB2.y * aB;
            accv[6] += fA3.x * aA + fB3.x * aB;
            accv[7] += fA3.y * aA + fB3.y * aB;
        }
        if (j < nn) {
            int s = __shfl_sync(0xffffffffu, sreg, j);
            float wgt = 0.f;
            if (lane < 8) wgt = __expf(lrelu(asrc[s * 8 + lane] + ad));
            den += wgt;
            float a = __shfl_sync(0xffffffffu, wgt, h0);
            uint4 r = *reinterpret_cast<const uint4*>(h1h + (size_t)s * 256 + lane * 8);
            float2 f0 = __half22float2(*reinterpret_cast<__half2*>(&r.x));
            float2 f1 = __half22float2(*reinterpret_cast<__half2*>(&r.y));
            float2 f2 = __half22float2(*reinterpret_cast<__half2*>(&r.z));
            float2 f3 = __half22float2(*reinterpret_cast<__half2*>(&r.w));
            accv[0] += f0.x * a; accv[1] += f0.y * a;
            accv[2] += f1.x * a; accv[3] += f1.y * a;
            accv[4] += f2.x * a; accv[5] += f2.y * a;
            accv[6] += f3.x * a; accv[7] += f3.y * a;
        }
    }
    float dn = __shfl_sync(0xffffffffu, den, h0);
    float rs = 1.f / dn;
    const float4* bp = reinterpret_cast<const float4*>(b1 + lane * 8);
    float4 bb0 = bp[0], bb1 = bp[1];
    float o[8];
    o[0] = eluf(accv[0] * rs + bb0.x); o[1] = eluf(accv[1] * rs + bb0.y);
    o[2] = eluf(accv[2] * rs + bb0.z); o[3] = eluf(accv[3] * rs + bb0.w);
    o[4] = eluf(accv[4] * rs + bb1.x); o[5] = eluf(accv[5] * rs + bb1.y);
    o[6] = eluf(accv[6] * rs + bb1.z); o[7] = eluf(accv[7] * rs + bb1.w);
    __half2 p0 = __floats2half2_rn(o[0], o[1]);
    __half2 p1 = __floats2half2_rn(o[2], o[3]);
    __half2 p2 = __floats2half2_rn(o[4], o[5]);
    __half2 p3 = __floats2half2_rn(o[6], o[7]);
    uint4 pk;
    pk.x = *reinterpret_cast<unsigned*>(&p0);
    pk.y = *reinterpret_cast<unsigned*>(&p1);
    pk.z = *reinterpret_cast<unsigned*>(&p2);
    pk.w = *reinterpret_cast<unsigned*>(&p3);
    *reinterpret_cast<uint4*>(out1h + (size_t)d * 256 + lane * 8) = pk;
}

// ----- GEMM2: h2 = x2[N,256] @ W2[256,16], fp16 in/out, fused alpha2 ---------
__global__ void k_gemm2(const __half* __restrict__ x2h, const float* __restrict__ W2,
                        const float* __restrict__ a_src2, const float* __restrict__ a_dst2,
                        __half* __restrict__ h2h, float* __restrict__ asrc2n,
                        float* __restrict__ adst2n, int N) {
    __shared__ float Wsh[256 * 16];
    int t = threadIdx.x;
    for (int i = t; i < 4096; i += 256) Wsh[i] = W2[i];
    __syncthreads();
    int n = blockIdx.x * 16 + (t >> 4);
    int c = t & 15;
    if (n >= N) return;
    float acc = 0.f;
    const __half2* xr = reinterpret_cast<const __half2*>(x2h + (size_t)n * 256);
#pragma unroll 16
    for (int k2 = 0; k2 < 128; k2++) {
        float2 xv = __half22float2(xr[k2]);
        acc += xv.x * Wsh[(2 * k2) * 16 + c] + xv.y * Wsh[(2 * k2 + 1) * 16 + c];
    }
    h2h[(size_t)n * 16 + c] = __float2half(acc);
    float r1 = acc * a_src2[c];
    float r2 = acc * a_dst2[c];
#pragma unroll
    for (int m = 8; m >= 1; m >>= 1) {
        r1 += __shfl_xor_sync(0xffffffffu, r1, m, 16);
        r2 += __shfl_xor_sync(0xffffffffu, r2, m, 16);
    }
    if (c == 0) { asrc2n[n] = r1; adst2n[n] = r2; }
}

// ----- GAT2 pull aggregation + fused GCN transform (h3) ----------------------
// 4 lanes per dst. After computing the ELU'd out2 row, exchange within the
// 4-lane group and apply W3 + dinv to produce g directly (fp16).
__global__ void k_agg2(const int* __restrict__ rowptr, const int* __restrict__ esrc,
                       const float* __restrict__ asrc, const float* __restrict__ adst,
                       const __half* __restrict__ h2h, const float* __restrict__ b2,
                       const float* __restrict__ W3, __half* __restrict__ gh, int N) {
    __shared__ float W3s[256];
    if (threadIdx.x < 256) W3s[threadIdx.x] = W3[threadIdx.x];
    __syncthreads();
    long long gt = (long long)blockIdx.x * blockDim.x + threadIdx.x;
    int d = (int)(gt >> 2);
    int q = threadIdx.x & 3;
    if (d >= N) return;
    int beg = rowptr[d], endp = rowptr[d + 1];
    float ad = adst[d];
    float den = 0.f;
    float4 acc = {0, 0, 0, 0};
    for (int idx = beg; idx < endp; idx++) {
        int s = esrc[idx];
        float wgt = __expf(lrelu(asrc[s] + ad));
        den += wgt;
        uint2 r = *reinterpret_cast<const uint2*>(h2h + (size_t)s * 16 + q * 4);
        float2 f0 = __half22float2(*reinterpret_cast<__half2*>(&r.x));
        float2 f1 = __half22float2(*reinterpret_cast<__half2*>(&r.y));
        acc.x += f0.x * wgt; acc.y += f0.y * wgt;
        acc.z += f1.x * wgt; acc.w += f1.y * wgt;
    }
    float rr = 1.f / den;
    float4 bb = reinterpret_cast<const float4*>(b2)[q];
    float4 o;
    o.x = eluf(acc.x * rr + bb.x); o.y = eluf(acc.y * rr + bb.y);
    o.z = eluf(acc.z * rr + bb.z); o.w = eluf(acc.w * rr + bb.w);

    // ---- fused h3: assemble full 16-vec across the 4-lane group ----
    float v[16];
#pragma unroll
    for (int r = 0; r < 4; r++) {
        v[r * 4 + 0] = __shfl_sync(0xffffffffu, o.x, r, 4);
        v[r * 4 + 1] = __shfl_sync(0xffffffffu, o.y, r, 4);
        v[r * 4 + 2] = __shfl_sync(0xffffffffu, o.z, r, 4);
        v[r * 4 + 3] = __shfl_sync(0xffffffffu, o.w, r, 4);
    }
    float dv = rsqrtf((float)(endp - beg));
    float gacc[4];
#pragma unroll
    for (int j = 0; j < 4; j++) {
        int cc = q * 4 + j;
        float a = 0.f;
#pragma unroll
        for (int k = 0; k < 16; k++) a += v[k] * W3s[k * 16 + cc];
        gacc[j] = a * dv;
    }
    __half2 p0 = __floats2half2_rn(gacc[0], gacc[1]);
    __half2 p1 = __floats2half2_rn(gacc[2], gacc[3]);
    uint2 pk;
    pk.x = *reinterpret_cast<unsigned*>(&p0);
    pk.y = *reinterpret_cast<unsigned*>(&p1);
    *reinterpret_cast<uint2*>(gh + (size_t)d * 16 + q * 4) = pk;
}

// ----- GCN pull aggregation + finalize (fp16 gather) --------------------------
__global__ void k_agg3(const int* __restrict__ rowptr, const int* __restrict__ esrc,
                       const __half* __restrict__ gh, const float* __restrict__ b3,
                       float* __restrict__ out, int N) {
    long long gt = (long long)blockIdx.x * blockDim.x + threadIdx.x;
    int d = (int)(gt >> 2);
    int q = threadIdx.x & 3;
    if (d >= N) return;
    int beg = rowptr[d], endp = rowptr[d + 1];
    float4 acc = {0, 0, 0, 0};
    for (int idx = beg; idx < endp; idx++) {
        int s = esrc[idx];
        uint2 r = *reinterpret_cast<const uint2*>(gh + (size_t)s * 16 + q * 4);
        float2 f0 = __half22float2(*reinterpret_cast<__half2*>(&r.x));
        float2 f1 = __half22float2(*reinterpret_cast<__half2*>(&r.y));
        acc.x += f0.x; acc.y += f0.y; acc.z += f1.x; acc.w += f1.y;
    }
    float dv = rsqrtf((float)(endp - beg));
    float4 bb = reinterpret_cast<const float4*>(b3)[q];
    float4 o;
    o.x = acc.x * dv + bb.x; o.y = acc.y * dv + bb.y;
    o.z = acc.z * dv + bb.z; o.w = acc.w * dv + bb.w;
    reinterpret_cast<float4*>(out + (size_t)d * 16)[q] = o;
}

// ---------------------------------------------------------------------------
extern "C" void kernel_launch(void* const* d_in, const int* in_sizes, int n_in,
                              void* d_out, int out_size) {
    const float* x      = (const float*)d_in[0];
    const int*   ei     = (const int*)d_in[1];
    const float* W1     = (const float*)d_in[2];
    const float* a_src1 = (const float*)d_in[3];
    const float* a_dst1 = (const float*)d_in[4];
    const float* b1     = (const float*)d_in[5];
    const float* W2     = (const float*)d_in[6];
    const float* a_src2 = (const float*)d_in[7];
    const float* a_dst2 = (const float*)d_in[8];
    const float* b2     = (const float*)d_in[9];
    const float* W3     = (const float*)d_in[10];
    const float* b3     = (const float*)d_in[11];
    float* out = (float*)d_out;

    const int N = in_sizes[0] / 128;
    const int E = in_sizes[1] / 2;
    const int ET = E + N;

    float *asrc1, *adst1, *asrc2, *adst2;
    __half *h1h, *out1h, *h2h, *gh;
    int *degi, *cursor, *rowptr, *esrc;
    float2 *xsp, *wsp;
    void* p;
    cudaGetSymbolAddress(&p, g_h1h);    h1h    = (__half*)p;
    cudaGetSymbolAddress(&p, g_asrc1);  asrc1  = (float*)p;
    cudaGetSymbolAddress(&p, g_adst1);  adst1  = (float*)p;
    cudaGetSymbolAddress(&p, g_out1h);  out1h  = (__half*)p;
    cudaGetSymbolAddress(&p, g_h2h);    h2h    = (__half*)p;
    cudaGetSymbolAddress(&p, g_asrc2);  asrc2  = (float*)p;
    cudaGetSymbolAddress(&p, g_adst2);  adst2  = (float*)p;
    cudaGetSymbolAddress(&p, g_gh);     gh     = (__half*)p;
    cudaGetSymbolAddress(&p, g_degi);   degi   = (int*)p;
    cudaGetSymbolAddress(&p, g_cursor); cursor = (int*)p;
    cudaGetSymbolAddress(&p, g_rowptr); rowptr = (int*)p;
    cudaGetSymbolAddress(&p, g_esrc);   esrc   = (int*)p;
    cudaGetSymbolAddress(&p, g_xsp);    xsp    = (float2*)p;
    cudaGetSymbolAddress(&p, g_wsp);    wsp    = (float2*)p;

    static cudaStream_t s2 = nullptr;
    static cudaEvent_t evFork = nullptr, evJoin = nullptr, evW = nullptr;
    static int smem_set = 0;
    if (!s2) {
        cudaStreamCreateWithFlags(&s2, cudaStreamNonBlocking);
        cudaEventCreateWithFlags(&evFork, cudaEventDisableTiming);
        cudaEventCreateWithFlags(&evJoin, cudaEventDisableTiming);
        cudaEventCreateWithFlags(&evW, cudaEventDisableTiming);
    }
    if (!smem_set) {
        cudaFuncSetAttribute(k_gemm1_tc2,
                             cudaFuncAttributeMaxDynamicSharedMemorySize,
                             SMEM_F2 * (int)sizeof(float2));
        smem_set = 1;
    }

    const int B = 256;

    // ---- fork: W1 split + CSR chain on s2, concurrent with x split ----
    cudaEventRecord(evFork, 0);
    cudaStreamWaitEvent(s2, evFork, 0);

    k_split<<<(8192 + B - 1) / B, B, 0, s2>>>(W1, wsp, 8192);
    cudaEventRecord(evW, s2);
    cudaMemsetAsync(degi,   0, (size_t)N * sizeof(int), s2);
    cudaMemsetAsync(cursor, 0, (size_t)N * sizeof(int), s2);
    k_deg<<<(ET + B - 1) / B, B, 0, s2>>>(ei, E, N, degi);
    k_scan<<<1, 1024, 0, s2>>>(degi, rowptr, N, ET);
    k_fill<<<(ET + B - 1) / B, B, 0, s2>>>(ei, E, N, rowptr, cursor, esrc);
    cudaEventRecord(evJoin, s2);

    // main stream: x split, then tensor-core GEMM1 (needs wsp)
    k_split<<<(N * 32 + B - 1) / B, B>>>(x, xsp, N * 32);
    cudaStreamWaitEvent(0, evW, 0);
    {
        dim3 grid((N + 127) / 128, 2);
        k_gemm1_tc2<<<grid, 256, SMEM_F2 * sizeof(float2)>>>(
            xsp, wsp, a_src1, a_dst1, h1h, asrc1, adst1, N);
    }

    // ---- join: agg1 needs CSR ----
    cudaStreamWaitEvent(0, evJoin, 0);

    {
        long long tot = (long long)N * 32;   // warp per dst
        k_agg1<<<(unsigned)((tot + B - 1) / B), B>>>(rowptr, esrc, asrc1, adst1, h1h, b1, out1h, N);
    }

    // Layer 2: GAT(256 -> 16, 1 head)
    k_gemm2<<<(N + 15) / 16, B>>>(out1h, W2, a_src2, a_dst2, h2h, asrc2, adst2, N);
    {
        long long tot = (long long)N * 4;
        k_agg2<<<(unsigned)((tot + B - 1) / B), B>>>(rowptr, esrc, asrc2, adst2, h2h, b2, W3, gh, N);
    }

    // Layer 3: GCN aggregation + finalize
    {
        long long tot = (long long)N * 4;
        k_agg3<<<(unsigned)((tot + B - 1) / B), B>>>(rowptr, esrc, gh, b3, out, N);
    }
}